// round 1
// baseline (speedup 1.0000x reference)
#include <cuda_runtime.h>

#define NN 8192
#define NE 262144
#define FIN 512
#define H1D 256
#define H2D 128
#define H3D 64
#define O6 6

// ---------------- device scratch (no allocations allowed) ----------------
__device__ float g_xw1[NN * H1D];      // x @ W1
__device__ float g_h1[NN * H1D];       // relu(A @ xw1)
__device__ float g_ah1[NN * H1D];      // A @ h1
__device__ float g_ml[NN * H2D];       // ah1 @ Wcat  (mu|logvar pre-bias)
__device__ float g_Wcat[H1D * H2D];    // [W2@dense_W | W3@dense_W]
__device__ int   g_cnt[NN];
__device__ int   g_rp[NN + 1];
__device__ int   g_cols[NE];
__device__ float g_vals[NE];

// ---------------- generic 64x64-tile SGEMM (row-major C = A@B) ----------------
__global__ void sgemm64(const float* __restrict__ A, const float* __restrict__ B,
                        float* __restrict__ C, int M, int N, int K) {
    __shared__ float As[16][65];
    __shared__ float Bs[16][65];
    int tid = threadIdx.x;
    int tx = tid & 15, ty = tid >> 4;
    int row0 = blockIdx.y * 64, col0 = blockIdx.x * 64;
    float acc[4][4];
#pragma unroll
    for (int r = 0; r < 4; r++)
#pragma unroll
        for (int c = 0; c < 4; c++) acc[r][c] = 0.f;

    for (int k0 = 0; k0 < K; k0 += 16) {
#pragma unroll
        for (int i = tid; i < 1024; i += 256) {
            int m = i >> 4, kk = i & 15;
            As[kk][m] = A[(size_t)(row0 + m) * K + k0 + kk];
        }
#pragma unroll
        for (int i = tid; i < 1024; i += 256) {
            int kk = i >> 6, n = i & 63;
            Bs[kk][n] = B[(size_t)(k0 + kk) * N + col0 + n];
        }
        __syncthreads();
#pragma unroll
        for (int kk = 0; kk < 16; kk++) {
            float a[4], b[4];
#pragma unroll
            for (int r = 0; r < 4; r++) a[r] = As[kk][ty * 4 + r];
#pragma unroll
            for (int c = 0; c < 4; c++) b[c] = Bs[kk][tx * 4 + c];
#pragma unroll
            for (int r = 0; r < 4; r++)
#pragma unroll
                for (int c = 0; c < 4; c++) acc[r][c] += a[r] * b[c];
        }
        __syncthreads();
    }
#pragma unroll
    for (int r = 0; r < 4; r++) {
        float4 v = make_float4(acc[r][0], acc[r][1], acc[r][2], acc[r][3]);
        *(float4*)&C[(size_t)(row0 + ty * 4 + r) * N + col0 + tx * 4] = v;
    }
}

// ---------------- CSR build ----------------
__global__ void hist_kernel(const int* __restrict__ rows) {
    int e = blockIdx.x * 256 + threadIdx.x;
    if (e < NE) atomicAdd(&g_cnt[rows[e]], 1);
}

__global__ void scan_kernel() {
    __shared__ int s[1024];
    int t = threadIdx.x;
    int loc[8];
    int tot = 0;
#pragma unroll
    for (int j = 0; j < 8; j++) { loc[j] = g_cnt[t * 8 + j]; tot += loc[j]; }
    s[t] = tot;
    __syncthreads();
    for (int off = 1; off < 1024; off <<= 1) {
        int v = (t >= off) ? s[t - off] : 0;
        __syncthreads();
        s[t] += v;
        __syncthreads();
    }
    int base = s[t] - tot;
#pragma unroll
    for (int j = 0; j < 8; j++) { g_rp[t * 8 + j] = base; base += loc[j]; }
    if (t == 1023) g_rp[NN] = s[1023];
}

__global__ void scatter_kernel(const int* __restrict__ rows, const int* __restrict__ cols,
                               const float* __restrict__ vals) {
    int e = blockIdx.x * 256 + threadIdx.x;
    if (e < NE) {
        int r = rows[e];
        int pos = g_rp[r] + atomicAdd(&g_cnt[r], 1);
        g_cols[pos] = cols[e];
        g_vals[pos] = vals[e];
    }
}

// ---------------- SpMM: Y[r,:] = sum_e val * X[col,:]  (D=256, one block/row) ----------------
__global__ void spmm256(const float* __restrict__ X, float* __restrict__ Y, int relu) {
    int r = blockIdx.x;
    int t = threadIdx.x;
    int s = g_rp[r], e = g_rp[r + 1];
    float acc = 0.f;
    int i = s;
    for (; i + 1 < e; i += 2) {
        int c0 = g_cols[i], c1 = g_cols[i + 1];
        float v0 = g_vals[i], v1 = g_vals[i + 1];
        acc += v0 * X[(size_t)c0 * 256 + t];
        acc += v1 * X[(size_t)c1 * 256 + t];
    }
    if (i < e) acc += g_vals[i] * X[(size_t)g_cols[i] * 256 + t];
    Y[(size_t)r * 256 + t] = relu ? fmaxf(acc, 0.f) : acc;
}

// ---------------- Wcat = [W2@dense_W | W3@dense_W]  (256 x 128) ----------------
__global__ void wcat_kernel(const float* __restrict__ W2, const float* __restrict__ W3,
                            const float* __restrict__ dW) {
    int k = blockIdx.x;      // 0..255
    int c = threadIdx.x;     // 0..127
    const float* Ws = (c < 64) ? W2 : W3;
    int cc = c & 63;
    float a = 0.f;
#pragma unroll 4
    for (int j = 0; j < H2D; j++) a += Ws[k * H2D + j] * dW[j * H3D + cc];
    g_Wcat[k * H2D + c] = a;
}

// ---------------- epilogue: mu, logvar (+bias), out6 ----------------
__global__ void epilogue_kernel(const float* __restrict__ db, const float* __restrict__ d1W,
                                const float* __restrict__ d1b,
                                float* __restrict__ mu, float* __restrict__ lv,
                                float* __restrict__ o6) {
    int r = blockIdx.x;
    int t = threadIdx.x;  // 64
    float b = db[t];
    float m = g_ml[(size_t)r * 128 + t] + b;
    float l = g_ml[(size_t)r * 128 + 64 + t] + b;
    mu[(size_t)r * 64 + t] = m;
    lv[(size_t)r * 64 + t] = l;
    __shared__ float sm[64];
    sm[t] = m;
    __syncthreads();
    if (t < O6) {
        float a = d1b[t];
#pragma unroll
        for (int k = 0; k < 64; k++) a += sm[k] * d1W[k * O6 + t];
        o6[(size_t)r * O6 + t] = a;
    }
}

// ---------------- adj_rec = Z @ Z^T  (symmetric: compute lower tri, mirror) ----------------
__global__ void zzt_kernel(const float* __restrict__ Z, float* __restrict__ C) {
    int bx = blockIdx.x, by = blockIdx.y;
    if (by > bx) return;  // only by <= bx
    __shared__ float As[64][65];  // rows by*64..   (also reused as transpose buffer)
    __shared__ float Bs[64][65];  // rows bx*64..
    int tid = threadIdx.x;
#pragma unroll
    for (int i = tid; i < 4096; i += 256) {
        int r = i >> 6, c = i & 63;
        As[r][c] = Z[(size_t)(by * 64 + r) * 64 + c];
        Bs[r][c] = Z[(size_t)(bx * 64 + r) * 64 + c];
    }
    __syncthreads();
    int tx = tid & 15, ty = tid >> 4;
    float acc[4][4];
#pragma unroll
    for (int r = 0; r < 4; r++)
#pragma unroll
        for (int c = 0; c < 4; c++) acc[r][c] = 0.f;
#pragma unroll
    for (int k = 0; k < 64; k++) {
        float a[4], b[4];
#pragma unroll
        for (int r = 0; r < 4; r++) a[r] = As[ty * 4 + r][k];
#pragma unroll
        for (int c = 0; c < 4; c++) b[c] = Bs[tx * 4 + c][k];
#pragma unroll
        for (int r = 0; r < 4; r++)
#pragma unroll
            for (int c = 0; c < 4; c++) acc[r][c] += a[r] * b[c];
    }
    int i0 = by * 64, j0 = bx * 64;
    // direct tile: C[i0+m][j0+n]
#pragma unroll
    for (int r = 0; r < 4; r++) {
        float4 v = make_float4(acc[r][0], acc[r][1], acc[r][2], acc[r][3]);
        *(float4*)&C[(size_t)(i0 + ty * 4 + r) * NN + j0 + tx * 4] = v;
    }
    if (bx != by) {
        __syncthreads();  // done reading As
#pragma unroll
        for (int r = 0; r < 4; r++)
#pragma unroll
            for (int c = 0; c < 4; c++) As[ty * 4 + r][tx * 4 + c] = acc[r][c];
        __syncthreads();
        // mirror tile: C[j0+jl][i0+il] = T[il][jl]
#pragma unroll
        for (int r = 0; r < 4; r++) {
            int jl = ty * 4 + r;
            float4 v = make_float4(As[tx * 4 + 0][jl], As[tx * 4 + 1][jl],
                                   As[tx * 4 + 2][jl], As[tx * 4 + 3][jl]);
            *(float4*)&C[(size_t)(j0 + jl) * NN + i0 + tx * 4] = v;
        }
    }
}

// ---------------- launch ----------------
extern "C" void kernel_launch(void* const* d_in, const int* in_sizes, int n_in,
                              void* d_out, int out_size) {
    const float* x        = (const float*)d_in[0];
    const int*   adj_rows = (const int*)d_in[1];
    const int*   adj_cols = (const int*)d_in[2];
    const float* adj_vals = (const float*)d_in[3];
    const float* W1       = (const float*)d_in[4];
    const float* W2       = (const float*)d_in[5];
    const float* W3       = (const float*)d_in[6];
    const float* dense_W  = (const float*)d_in[7];
    const float* dense_b  = (const float*)d_in[8];
    const float* dense1_W = (const float*)d_in[9];
    const float* dense1_b = (const float*)d_in[10];

    float* out  = (float*)d_out;
    float* adj  = out;                               // [N, N]
    float* o6   = adj + (size_t)NN * NN;             // [N, 6]
    float* mu   = o6 + (size_t)NN * O6;              // [N, 64]
    float* lv   = mu + (size_t)NN * H3D;             // [N, 64]

    void *p_xw1, *p_h1, *p_ah1, *p_ml, *p_wcat, *p_cnt;
    cudaGetSymbolAddress(&p_xw1, g_xw1);
    cudaGetSymbolAddress(&p_h1, g_h1);
    cudaGetSymbolAddress(&p_ah1, g_ah1);
    cudaGetSymbolAddress(&p_ml, g_ml);
    cudaGetSymbolAddress(&p_wcat, g_Wcat);
    cudaGetSymbolAddress(&p_cnt, g_cnt);

    // 1) xw1 = x @ W1   (8192 x 512 @ 512 x 256)
    sgemm64<<<dim3(H1D / 64, NN / 64), 256>>>(x, W1, (float*)p_xw1, NN, H1D, FIN);

    // 2) CSR build
    cudaMemsetAsync(p_cnt, 0, NN * sizeof(int));
    hist_kernel<<<NE / 256, 256>>>(adj_rows);
    scan_kernel<<<1, 1024>>>();
    cudaMemsetAsync(p_cnt, 0, NN * sizeof(int));
    scatter_kernel<<<NE / 256, 256>>>(adj_rows, adj_cols, adj_vals);

    // 3) h1 = relu(A @ xw1); ah1 = A @ h1
    spmm256<<<NN, 256>>>((const float*)p_xw1, (float*)p_h1, 1);
    spmm256<<<NN, 256>>>((const float*)p_h1, (float*)p_ah1, 0);

    // 4) Wcat = [W2@dense_W | W3@dense_W];  ml = ah1 @ Wcat
    wcat_kernel<<<H1D, H2D>>>(W2, W3, dense_W);
    sgemm64<<<dim3(H2D / 64, NN / 64), 256>>>((const float*)p_ah1, (const float*)p_wcat,
                                              (float*)p_ml, NN, H2D, H1D);

    // 5) mu / logvar / out6
    epilogue_kernel<<<NN, 64>>>(dense_b, dense1_W, dense1_b, mu, lv, o6);

    // 6) adj_rec = mu @ mu^T (symmetric)
    zzt_kernel<<<dim3(NN / 64, NN / 64), 256>>>(mu, adj);
}

// round 2
// speedup vs baseline: 1.2028x; 1.2028x over previous
#include <cuda_runtime.h>

#define NN 8192
#define NE 262144
#define FIN 512
#define H1D 256
#define H2D 128
#define H3D 64
#define O6 6

// ---------------- device scratch (no allocations allowed) ----------------
__device__ float g_xw1[NN * H1D];      // x @ W1
__device__ float g_h1[NN * H1D];       // relu(A @ xw1)
__device__ float g_ah1[NN * H1D];      // A @ h1
__device__ float g_ml[NN * H2D];       // ah1 @ Wcat  (mu|logvar pre-bias)
__device__ float g_Wcat[H1D * H2D];    // [W2@dense_W | W3@dense_W]
__device__ int   g_cnt[NN];
__device__ int   g_rp[NN + 1];
__device__ int2  g_colval[NE];         // packed (col, val-bits)

// ================= generic SGEMM: BM=128, BK=16, TM=8, 256 threads =================
// C[M,N] = A[M,K] @ B[K,N], row-major. BN/TN select 128x8 or 64x4 variants.
template <int BN, int TN>
__global__ void sgemm_tmpl(const float* __restrict__ A, const float* __restrict__ B,
                           float* __restrict__ C, int M, int N, int K) {
    const int BM = 128, BK = 16, TM = 8;
    __shared__ float As[BK][132];
    __shared__ float Bs[BK][BN + 4];
    int tid = threadIdx.x;
    const int ncol = BN / TN;              // 16 for both variants
    int tx = tid % ncol, ty = tid / ncol;  // ty: 0..15
    int row0 = blockIdx.y * BM, col0 = blockIdx.x * BN;

    float acc[TM][TN];
#pragma unroll
    for (int r = 0; r < TM; r++)
#pragma unroll
        for (int c = 0; c < TN; c++) acc[r][c] = 0.f;

    for (int k0 = 0; k0 < K; k0 += BK) {
        // load A tile 128x16, store transposed As[k][m]
#pragma unroll
        for (int i = 0; i < 2; i++) {
            int idx = tid + i * 256;          // 0..511 float4s
            int ar = idx >> 2, kq = (idx & 3) * 4;
            float4 v = *(const float4*)&A[(size_t)(row0 + ar) * K + k0 + kq];
            As[kq + 0][ar] = v.x; As[kq + 1][ar] = v.y;
            As[kq + 2][ar] = v.z; As[kq + 3][ar] = v.w;
        }
        // load B tile 16xBN directly
#pragma unroll
        for (int i = 0; i < (BK * BN) / 1024; i++) {
            int idx = tid + i * 256;
            int br = idx / (BN / 4), bc = (idx % (BN / 4)) * 4;
            *(float4*)&Bs[br][bc] = *(const float4*)&B[(size_t)(k0 + br) * N + col0 + bc];
        }
        __syncthreads();
#pragma unroll
        for (int kk = 0; kk < BK; kk++) {
            float a[TM], b[TN];
            *(float4*)&a[0] = *(float4*)&As[kk][ty * 8];
            *(float4*)&a[4] = *(float4*)&As[kk][ty * 8 + 4];
            *(float4*)&b[0] = *(float4*)&Bs[kk][tx * TN];
            if (TN == 8) *(float4*)&b[4] = *(float4*)&Bs[kk][tx * TN + 4];
#pragma unroll
            for (int r = 0; r < TM; r++)
#pragma unroll
                for (int c = 0; c < TN; c++) acc[r][c] += a[r] * b[c];
        }
        __syncthreads();
    }
#pragma unroll
    for (int r = 0; r < TM; r++) {
        size_t off = (size_t)(row0 + ty * 8 + r) * N + col0 + tx * TN;
        *(float4*)&C[off] = make_float4(acc[r][0], acc[r][1], acc[r][2], acc[r][3]);
        if (TN == 8)
            *(float4*)&C[off + 4] = make_float4(acc[r][4], acc[r][5], acc[r][6], acc[r][7]);
    }
}

// ================= CSR build =================
__global__ void hist_kernel(const int* __restrict__ rows) {
    int i = blockIdx.x * 256 + threadIdx.x;     // over NE/4
    int4 r = ((const int4*)rows)[i];
    atomicAdd(&g_cnt[r.x], 1);
    atomicAdd(&g_cnt[r.y], 1);
    atomicAdd(&g_cnt[r.z], 1);
    atomicAdd(&g_cnt[r.w], 1);
}

__global__ void scan_kernel() {
    __shared__ int s[1024];
    int t = threadIdx.x;
    int loc[8];
    int tot = 0;
#pragma unroll
    for (int j = 0; j < 8; j++) { loc[j] = g_cnt[t * 8 + j]; tot += loc[j]; }
    s[t] = tot;
    __syncthreads();
    for (int off = 1; off < 1024; off <<= 1) {
        int v = (t >= off) ? s[t - off] : 0;
        __syncthreads();
        s[t] += v;
        __syncthreads();
    }
    int base = s[t] - tot;
#pragma unroll
    for (int j = 0; j < 8; j++) { g_rp[t * 8 + j] = base; base += loc[j]; }
    if (t == 1023) g_rp[NN] = s[1023];
}

__global__ void scatter_kernel(const int* __restrict__ rows, const int* __restrict__ cols,
                               const float* __restrict__ vals) {
    int e = blockIdx.x * 256 + threadIdx.x;
    int r = rows[e];
    int pos = g_rp[r] + atomicAdd(&g_cnt[r], 1);
    g_colval[pos] = make_int2(cols[e], __float_as_int(vals[e]));
}

// ================= SpMM: Y[r,:] = sum val * X[col,:], D=256, one block/row =================
__global__ void spmm256(const float* __restrict__ X, float* __restrict__ Y, int relu) {
    int r = blockIdx.x;
    int t = threadIdx.x;
    int s = g_rp[r], e = g_rp[r + 1];
    float acc = 0.f;
    int i = s;
    for (; i + 4 <= e; i += 4) {
        int2 c0 = g_colval[i], c1 = g_colval[i + 1], c2 = g_colval[i + 2], c3 = g_colval[i + 3];
        acc += __int_as_float(c0.y) * X[(size_t)c0.x * 256 + t];
        acc += __int_as_float(c1.y) * X[(size_t)c1.x * 256 + t];
        acc += __int_as_float(c2.y) * X[(size_t)c2.x * 256 + t];
        acc += __int_as_float(c3.y) * X[(size_t)c3.x * 256 + t];
    }
    for (; i < e; i++) {
        int2 c = g_colval[i];
        acc += __int_as_float(c.y) * X[(size_t)c.x * 256 + t];
    }
    Y[(size_t)r * 256 + t] = relu ? fmaxf(acc, 0.f) : acc;
}

// ================= Wcat = [W2@dense_W | W3@dense_W] (256 x 128) =================
__global__ void wcat_kernel(const float* __restrict__ W2, const float* __restrict__ W3,
                            const float* __restrict__ dW) {
    int k = blockIdx.x;      // 0..255
    int c = threadIdx.x;     // 0..127
    const float* Ws = (c < 64) ? W2 : W3;
    int cc = c & 63;
    float a = 0.f;
#pragma unroll 4
    for (int j = 0; j < H2D; j++) a += Ws[k * H2D + j] * dW[j * H3D + cc];
    g_Wcat[k * H2D + c] = a;
}

// ================= epilogue: mu, logvar (+bias), out6 =================
__global__ void epilogue_kernel(const float* __restrict__ db, const float* __restrict__ d1W,
                                const float* __restrict__ d1b,
                                float* __restrict__ mu, float* __restrict__ lv,
                                float* __restrict__ o6) {
    int r = blockIdx.x;
    int t = threadIdx.x;  // 64
    float b = db[t];
    float m = g_ml[(size_t)r * 128 + t] + b;
    float l = g_ml[(size_t)r * 128 + 64 + t] + b;
    mu[(size_t)r * 64 + t] = m;
    lv[(size_t)r * 64 + t] = l;
    __shared__ float sm[64];
    sm[t] = m;
    __syncthreads();
    if (t < O6) {
        float a = d1b[t];
#pragma unroll
        for (int k = 0; k < 64; k++) a += sm[k] * d1W[k * O6 + t];
        o6[(size_t)r * O6 + t] = a;
    }
}

// ================= adj_rec = Z @ Z^T, 128x128 tiles, symmetric mirror =================
__global__ void zzt_kernel(const float* __restrict__ Z, float* __restrict__ C) {
    int bx = blockIdx.x, by = blockIdx.y;
    if (by > bx) return;
    __shared__ float sm[4300];
    float (*As)[132] = (float(*)[132])sm;
    float (*Bs)[132] = (float(*)[132])(sm + 16 * 132);
    int tid = threadIdx.x;
    int tx = tid & 15, ty = tid >> 4;
    int i0 = by * 128, j0 = bx * 128;

    float acc[8][8];
#pragma unroll
    for (int r = 0; r < 8; r++)
#pragma unroll
        for (int c = 0; c < 8; c++) acc[r][c] = 0.f;

    for (int k0 = 0; k0 < 64; k0 += 16) {
#pragma unroll
        for (int i = 0; i < 2; i++) {
            int idx = tid + i * 256;
            int row = idx >> 2, kq = (idx & 3) * 4;
            float4 va = *(const float4*)&Z[(size_t)(i0 + row) * 64 + k0 + kq];
            As[kq + 0][row] = va.x; As[kq + 1][row] = va.y;
            As[kq + 2][row] = va.z; As[kq + 3][row] = va.w;
            float4 vb = *(const float4*)&Z[(size_t)(j0 + row) * 64 + k0 + kq];
            Bs[kq + 0][row] = vb.x; Bs[kq + 1][row] = vb.y;
            Bs[kq + 2][row] = vb.z; Bs[kq + 3][row] = vb.w;
        }
        __syncthreads();
#pragma unroll
        for (int kk = 0; kk < 16; kk++) {
            float a[8], b[8];
            *(float4*)&a[0] = *(float4*)&As[kk][ty * 8];
            *(float4*)&a[4] = *(float4*)&As[kk][ty * 8 + 4];
            *(float4*)&b[0] = *(float4*)&Bs[kk][tx * 8];
            *(float4*)&b[4] = *(float4*)&Bs[kk][tx * 8 + 4];
#pragma unroll
            for (int r = 0; r < 8; r++)
#pragma unroll
                for (int c = 0; c < 8; c++) acc[r][c] += a[r] * b[c];
        }
        __syncthreads();
    }
    // direct tile: C[i0+ty*8+r][j0+tx*8+c]
#pragma unroll
    for (int r = 0; r < 8; r++) {
        size_t off = (size_t)(i0 + ty * 8 + r) * NN + j0 + tx * 8;
        *(float4*)&C[off] = make_float4(acc[r][0], acc[r][1], acc[r][2], acc[r][3]);
        *(float4*)&C[off + 4] = make_float4(acc[r][4], acc[r][5], acc[r][6], acc[r][7]);
    }
    if (bx == by) return;

    // mirror tile via smem transpose, 4 rounds of 32 columns
    float (*trs)[133] = (float(*)[133])sm;  // 32 x 133 = 4256 <= 4300
#pragma unroll
    for (int t = 0; t < 4; t++) {
        __syncthreads();
        if ((tx >> 2) == t) {
            int jb = (tx & 3) * 8;
#pragma unroll
            for (int c = 0; c < 8; c++)
#pragma unroll
                for (int r = 0; r < 8; r++) trs[jb + c][ty * 8 + r] = acc[r][c];
        }
        __syncthreads();
        int jj = tid >> 3;            // 0..31
        int ib = (tid & 7) * 16;      // 0..112
        size_t base = (size_t)(j0 + t * 32 + jj) * NN + i0 + ib;
#pragma unroll
        for (int q = 0; q < 4; q++) {
            float4 v = make_float4(trs[jj][ib + q * 4 + 0], trs[jj][ib + q * 4 + 1],
                                   trs[jj][ib + q * 4 + 2], trs[jj][ib + q * 4 + 3]);
            *(float4*)&C[base + q * 4] = v;
        }
    }
}

// ================= launch =================
extern "C" void kernel_launch(void* const* d_in, const int* in_sizes, int n_in,
                              void* d_out, int out_size) {
    const float* x        = (const float*)d_in[0];
    const int*   adj_rows = (const int*)d_in[1];
    const int*   adj_cols = (const int*)d_in[2];
    const float* adj_vals = (const float*)d_in[3];
    const float* W1       = (const float*)d_in[4];
    const float* W2       = (const float*)d_in[5];
    const float* W3       = (const float*)d_in[6];
    const float* dense_W  = (const float*)d_in[7];
    const float* dense_b  = (const float*)d_in[8];
    const float* dense1_W = (const float*)d_in[9];
    const float* dense1_b = (const float*)d_in[10];

    float* out = (float*)d_out;
    float* adj = out;                               // [N, N]
    float* o6  = adj + (size_t)NN * NN;             // [N, 6]
    float* mu  = o6 + (size_t)NN * O6;              // [N, 64]
    float* lv  = mu + (size_t)NN * H3D;             // [N, 64]

    void *p_xw1, *p_h1, *p_ah1, *p_ml, *p_wcat, *p_cnt;
    cudaGetSymbolAddress(&p_xw1, g_xw1);
    cudaGetSymbolAddress(&p_h1, g_h1);
    cudaGetSymbolAddress(&p_ah1, g_ah1);
    cudaGetSymbolAddress(&p_ml, g_ml);
    cudaGetSymbolAddress(&p_wcat, g_Wcat);
    cudaGetSymbolAddress(&p_cnt, g_cnt);

    // 1) xw1 = x @ W1   (8192x256, K=512)
    sgemm_tmpl<128, 8><<<dim3(H1D / 128, NN / 128), 256>>>(x, W1, (float*)p_xw1, NN, H1D, FIN);

    // 2) CSR build
    cudaMemsetAsync(p_cnt, 0, NN * sizeof(int));
    hist_kernel<<<NE / 1024, 256>>>(adj_rows);
    scan_kernel<<<1, 1024>>>();
    cudaMemsetAsync(p_cnt, 0, NN * sizeof(int));
    scatter_kernel<<<NE / 256, 256>>>(adj_rows, adj_cols, adj_vals);

    // 3) h1 = relu(A @ xw1); ah1 = A @ h1
    spmm256<<<NN, 256>>>((const float*)p_xw1, (float*)p_h1, 1);
    spmm256<<<NN, 256>>>((const float*)p_h1, (float*)p_ah1, 0);

    // 4) Wcat = [W2@dense_W | W3@dense_W];  ml = ah1 @ Wcat  (8192x128, K=256)
    wcat_kernel<<<H1D, H2D>>>(W2, W3, dense_W);
    sgemm_tmpl<64, 4><<<dim3(H2D / 64, NN / 128), 256>>>((const float*)p_ah1, (const float*)p_wcat,
                                                         (float*)p_ml, NN, H2D, H1D);

    // 5) mu / logvar / out6
    epilogue_kernel<<<NN, 64>>>(dense_b, dense1_W, dense1_b, mu, lv, o6);

    // 6) adj_rec = mu @ mu^T (symmetric, lower tri + mirror)
    zzt_kernel<<<dim3(NN / 128, NN / 128), 256>>>(mu, adj);
}

// round 3
// speedup vs baseline: 1.2159x; 1.0109x over previous
#include <cuda_runtime.h>

#define NN 8192
#define NE 262144
#define FIN 512
#define H1D 256
#define H2D 128
#define H3D 64
#define O6 6

// ---------------- device scratch ----------------
__device__ float g_xw1[NN * H1D];
__device__ float g_h1[NN * H1D];
__device__ float g_ah1[NN * H1D];
__device__ float g_ml[NN * H2D];
__device__ float g_Wcat[H1D * H2D];
__device__ float g_w1t[H1D * FIN];     // W1 transposed [256][512]
__device__ int   g_cnt[NN];
__device__ int   g_rp[NN + 1];
__device__ int2  g_colval[NE];

// ---------------- tf32 helpers ----------------
__device__ __forceinline__ void tf32_split(float x, unsigned& hi, unsigned& lo) {
    unsigned h;
    asm("cvt.rna.tf32.f32 %0, %1;" : "=r"(h) : "f"(x));
    float lf = x - __uint_as_float(h);
    unsigned l;
    asm("cvt.rna.tf32.f32 %0, %1;" : "=r"(l) : "f"(lf));
    hi = h; lo = l;
}

__device__ __forceinline__ void mma_tf32(float* c, const unsigned* a, const unsigned* b) {
    asm volatile(
        "mma.sync.aligned.m16n8k8.row.col.f32.tf32.tf32.f32 "
        "{%0,%1,%2,%3}, {%4,%5,%6,%7}, {%8,%9}, {%0,%1,%2,%3};"
        : "+f"(c[0]), "+f"(c[1]), "+f"(c[2]), "+f"(c[3])
        : "r"(a[0]), "r"(a[1]), "r"(a[2]), "r"(a[3]), "r"(b[0]), "r"(b[1]));
}

#define SP 20  // smem row stride (floats) — conflict-free for frag pattern

// ================= NT tensor GEMM: C[M,N] = A[M,K] @ Bt[N,K]^T, tf32 split =================
// BM=BN=128, 256 threads (8 warps, 2x4), warp tile 64x32, frag m16n8k8.
__global__ void mma_nt_kernel(const float* __restrict__ A, const float* __restrict__ Bt,
                              float* __restrict__ C, int K, int N) {
    __shared__ float buf[4 * 128 * SP];
    float* As_hi = buf;
    float* As_lo = buf + 128 * SP;
    float* Bs_hi = buf + 2 * 128 * SP;
    float* Bs_lo = buf + 3 * 128 * SP;

    int tid = threadIdx.x;
    int lane = tid & 31, warp = tid >> 5;
    int wr = warp >> 2, wc = warp & 3;
    int lr = lane >> 2, lc = lane & 3;
    int i0 = blockIdx.y * 128, j0 = blockIdx.x * 128;

    float acc[4][4][4];
#pragma unroll
    for (int m = 0; m < 4; m++)
#pragma unroll
        for (int n = 0; n < 4; n++)
#pragma unroll
            for (int q = 0; q < 4; q++) acc[m][n][q] = 0.f;

    for (int kc = 0; kc < K; kc += 16) {
#pragma unroll
        for (int i = 0; i < 2; i++) {
            int idx = tid + i * 256;
            int r = idx >> 2, kq = (idx & 3) * 4;
            float4 va = *(const float4*)&A[(size_t)(i0 + r) * K + kc + kq];
            float4 vb = *(const float4*)&Bt[(size_t)(j0 + r) * K + kc + kq];
            unsigned h, l;
            tf32_split(va.x, h, l); As_hi[r * SP + kq + 0] = __uint_as_float(h); As_lo[r * SP + kq + 0] = __uint_as_float(l);
            tf32_split(va.y, h, l); As_hi[r * SP + kq + 1] = __uint_as_float(h); As_lo[r * SP + kq + 1] = __uint_as_float(l);
            tf32_split(va.z, h, l); As_hi[r * SP + kq + 2] = __uint_as_float(h); As_lo[r * SP + kq + 2] = __uint_as_float(l);
            tf32_split(va.w, h, l); As_hi[r * SP + kq + 3] = __uint_as_float(h); As_lo[r * SP + kq + 3] = __uint_as_float(l);
            tf32_split(vb.x, h, l); Bs_hi[r * SP + kq + 0] = __uint_as_float(h); Bs_lo[r * SP + kq + 0] = __uint_as_float(l);
            tf32_split(vb.y, h, l); Bs_hi[r * SP + kq + 1] = __uint_as_float(h); Bs_lo[r * SP + kq + 1] = __uint_as_float(l);
            tf32_split(vb.z, h, l); Bs_hi[r * SP + kq + 2] = __uint_as_float(h); Bs_lo[r * SP + kq + 2] = __uint_as_float(l);
            tf32_split(vb.w, h, l); Bs_hi[r * SP + kq + 3] = __uint_as_float(h); Bs_lo[r * SP + kq + 3] = __uint_as_float(l);
        }
        __syncthreads();
#pragma unroll
        for (int ks = 0; ks < 2; ks++) {
            int kb = ks * 8 + lc;
            unsigned a_hi[4][4], a_lo[4][4], b_hi[4][2], b_lo[4][2];
#pragma unroll
            for (int mf = 0; mf < 4; mf++) {
                int r0 = wr * 64 + mf * 16 + lr;
                a_hi[mf][0] = __float_as_uint(As_hi[r0 * SP + kb]);
                a_hi[mf][1] = __float_as_uint(As_hi[(r0 + 8) * SP + kb]);
                a_hi[mf][2] = __float_as_uint(As_hi[r0 * SP + kb + 4]);
                a_hi[mf][3] = __float_as_uint(As_hi[(r0 + 8) * SP + kb + 4]);
                a_lo[mf][0] = __float_as_uint(As_lo[r0 * SP + kb]);
                a_lo[mf][1] = __float_as_uint(As_lo[(r0 + 8) * SP + kb]);
                a_lo[mf][2] = __float_as_uint(As_lo[r0 * SP + kb + 4]);
                a_lo[mf][3] = __float_as_uint(As_lo[(r0 + 8) * SP + kb + 4]);
            }
#pragma unroll
            for (int nf = 0; nf < 4; nf++) {
                int n0 = wc * 32 + nf * 8 + lr;
                b_hi[nf][0] = __float_as_uint(Bs_hi[n0 * SP + kb]);
                b_hi[nf][1] = __float_as_uint(Bs_hi[n0 * SP + kb + 4]);
                b_lo[nf][0] = __float_as_uint(Bs_lo[n0 * SP + kb]);
                b_lo[nf][1] = __float_as_uint(Bs_lo[n0 * SP + kb + 4]);
            }
#pragma unroll
            for (int mf = 0; mf < 4; mf++)
#pragma unroll
                for (int nf = 0; nf < 4; nf++) {
                    mma_tf32(acc[mf][nf], a_hi[mf], b_hi[nf]);
                    mma_tf32(acc[mf][nf], a_hi[mf], b_lo[nf]);
                    mma_tf32(acc[mf][nf], a_lo[mf], b_hi[nf]);
                }
        }
        __syncthreads();
    }
#pragma unroll
    for (int mf = 0; mf < 4; mf++) {
        int r = i0 + wr * 64 + mf * 16 + lr;
#pragma unroll
        for (int nf = 0; nf < 4; nf++) {
            int j = j0 + wc * 32 + nf * 8 + 2 * lc;
            *(float2*)&C[(size_t)r * N + j] = make_float2(acc[mf][nf][0], acc[mf][nf][1]);
            *(float2*)&C[(size_t)(r + 8) * N + j] = make_float2(acc[mf][nf][2], acc[mf][nf][3]);
        }
    }
}

// ================= zzt = Z @ Z^T (K=64), symmetric, tf32 split tensor path =================
__global__ void zzt_mma_kernel(const float* __restrict__ Z, float* __restrict__ C) {
    int bx = blockIdx.x, by = blockIdx.y;
    if (by > bx) return;
    __shared__ float buf[4 * 128 * SP];
    float* As_hi = buf;
    float* As_lo = buf + 128 * SP;
    float* Bs_hi = buf + 2 * 128 * SP;
    float* Bs_lo = buf + 3 * 128 * SP;

    int tid = threadIdx.x;
    int lane = tid & 31, warp = tid >> 5;
    int wr = warp >> 2, wc = warp & 3;
    int lr = lane >> 2, lc = lane & 3;
    int i0 = by * 128, j0 = bx * 128;

    float acc[4][4][4];
#pragma unroll
    for (int m = 0; m < 4; m++)
#pragma unroll
        for (int n = 0; n < 4; n++)
#pragma unroll
            for (int q = 0; q < 4; q++) acc[m][n][q] = 0.f;

#pragma unroll
    for (int kc = 0; kc < 64; kc += 16) {
#pragma unroll
        for (int i = 0; i < 2; i++) {
            int idx = tid + i * 256;
            int r = idx >> 2, kq = (idx & 3) * 4;
            float4 va = *(const float4*)&Z[(size_t)(i0 + r) * 64 + kc + kq];
            float4 vb = *(const float4*)&Z[(size_t)(j0 + r) * 64 + kc + kq];
            unsigned h, l;
            tf32_split(va.x, h, l); As_hi[r * SP + kq + 0] = __uint_as_float(h); As_lo[r * SP + kq + 0] = __uint_as_float(l);
            tf32_split(va.y, h, l); As_hi[r * SP + kq + 1] = __uint_as_float(h); As_lo[r * SP + kq + 1] = __uint_as_float(l);
            tf32_split(va.z, h, l); As_hi[r * SP + kq + 2] = __uint_as_float(h); As_lo[r * SP + kq + 2] = __uint_as_float(l);
            tf32_split(va.w, h, l); As_hi[r * SP + kq + 3] = __uint_as_float(h); As_lo[r * SP + kq + 3] = __uint_as_float(l);
            tf32_split(vb.x, h, l); Bs_hi[r * SP + kq + 0] = __uint_as_float(h); Bs_lo[r * SP + kq + 0] = __uint_as_float(l);
            tf32_split(vb.y, h, l); Bs_hi[r * SP + kq + 1] = __uint_as_float(h); Bs_lo[r * SP + kq + 1] = __uint_as_float(l);
            tf32_split(vb.z, h, l); Bs_hi[r * SP + kq + 2] = __uint_as_float(h); Bs_lo[r * SP + kq + 2] = __uint_as_float(l);
            tf32_split(vb.w, h, l); Bs_hi[r * SP + kq + 3] = __uint_as_float(h); Bs_lo[r * SP + kq + 3] = __uint_as_float(l);
        }
        __syncthreads();
#pragma unroll
        for (int ks = 0; ks < 2; ks++) {
            int kb = ks * 8 + lc;
            unsigned a_hi[4][4], a_lo[4][4], b_hi[4][2], b_lo[4][2];
#pragma unroll
            for (int mf = 0; mf < 4; mf++) {
                int r0 = wr * 64 + mf * 16 + lr;
                a_hi[mf][0] = __float_as_uint(As_hi[r0 * SP + kb]);
                a_hi[mf][1] = __float_as_uint(As_hi[(r0 + 8) * SP + kb]);
                a_hi[mf][2] = __float_as_uint(As_hi[r0 * SP + kb + 4]);
                a_hi[mf][3] = __float_as_uint(As_hi[(r0 + 8) * SP + kb + 4]);
                a_lo[mf][0] = __float_as_uint(As_lo[r0 * SP + kb]);
                a_lo[mf][1] = __float_as_uint(As_lo[(r0 + 8) * SP + kb]);
                a_lo[mf][2] = __float_as_uint(As_lo[r0 * SP + kb + 4]);
                a_lo[mf][3] = __float_as_uint(As_lo[(r0 + 8) * SP + kb + 4]);
            }
#pragma unroll
            for (int nf = 0; nf < 4; nf++) {
                int n0 = wc * 32 + nf * 8 + lr;
                b_hi[nf][0] = __float_as_uint(Bs_hi[n0 * SP + kb]);
                b_hi[nf][1] = __float_as_uint(Bs_hi[n0 * SP + kb + 4]);
                b_lo[nf][0] = __float_as_uint(Bs_lo[n0 * SP + kb]);
                b_lo[nf][1] = __float_as_uint(Bs_lo[n0 * SP + kb + 4]);
            }
#pragma unroll
            for (int mf = 0; mf < 4; mf++)
#pragma unroll
                for (int nf = 0; nf < 4; nf++) {
                    mma_tf32(acc[mf][nf], a_hi[mf], b_hi[nf]);
                    mma_tf32(acc[mf][nf], a_hi[mf], b_lo[nf]);
                    mma_tf32(acc[mf][nf], a_lo[mf], b_hi[nf]);
                }
        }
        __syncthreads();
    }
    // direct tile
#pragma unroll
    for (int mf = 0; mf < 4; mf++) {
        int r = i0 + wr * 64 + mf * 16 + lr;
#pragma unroll
        for (int nf = 0; nf < 4; nf++) {
            int j = j0 + wc * 32 + nf * 8 + 2 * lc;
            *(float2*)&C[(size_t)r * NN + j] = make_float2(acc[mf][nf][0], acc[mf][nf][1]);
            *(float2*)&C[(size_t)(r + 8) * NN + j] = make_float2(acc[mf][nf][2], acc[mf][nf][3]);
        }
    }
    if (bx == by) return;

    // mirror via smem transpose, 32-col strips
    float (*T)[132] = (float(*)[132])buf;
#pragma unroll
    for (int s = 0; s < 4; s++) {
        __syncthreads();
        if (wc == s) {
#pragma unroll
            for (int mf = 0; mf < 4; mf++) {
                int rl = wr * 64 + mf * 16 + lr;
#pragma unroll
                for (int nf = 0; nf < 4; nf++) {
                    int cl = nf * 8 + 2 * lc;
                    T[cl][rl] = acc[mf][nf][0];
                    T[cl + 1][rl] = acc[mf][nf][1];
                    T[cl][rl + 8] = acc[mf][nf][2];
                    T[cl + 1][rl + 8] = acc[mf][nf][3];
                }
            }
        }
        __syncthreads();
        int jj = tid >> 3, seg = (tid & 7) * 16;
        size_t base = (size_t)(j0 + s * 32 + jj) * NN + i0 + seg;
#pragma unroll
        for (int q = 0; q < 4; q++)
            *(float4*)&C[base + q * 4] = *(float4*)&T[jj][seg + q * 4];
    }
}

// ================= transpose W1 [512,256] -> W1T [256,512] =================
__global__ void transpose_kernel(const float* __restrict__ W, float* __restrict__ WT,
                                 int R, int Ccols) {
    __shared__ float t[32][33];
    int c0 = blockIdx.x * 32, r0 = blockIdx.y * 32;
    int x = threadIdx.x, y = threadIdx.y;
#pragma unroll
    for (int i = 0; i < 32; i += 8) t[y + i][x] = W[(size_t)(r0 + y + i) * Ccols + c0 + x];
    __syncthreads();
#pragma unroll
    for (int i = 0; i < 32; i += 8) WT[(size_t)(c0 + y + i) * R + r0 + x] = t[x][y + i];
}

// ================= scalar 128xBN SGEMM (for small ml GEMM) =================
template <int BN, int TN>
__global__ void sgemm_tmpl(const float* __restrict__ A, const float* __restrict__ B,
                           float* __restrict__ C, int M, int N, int K) {
    const int BM = 128, BK = 16, TM = 8;
    __shared__ float As[BK][132];
    __shared__ float Bs[BK][BN + 4];
    int tid = threadIdx.x;
    const int ncol = BN / TN;
    int tx = tid % ncol, ty = tid / ncol;
    int row0 = blockIdx.y * BM, col0 = blockIdx.x * BN;
    float acc[TM][TN];
#pragma unroll
    for (int r = 0; r < TM; r++)
#pragma unroll
        for (int c = 0; c < TN; c++) acc[r][c] = 0.f;
    for (int k0 = 0; k0 < K; k0 += BK) {
#pragma unroll
        for (int i = 0; i < 2; i++) {
            int idx = tid + i * 256;
            int ar = idx >> 2, kq = (idx & 3) * 4;
            float4 v = *(const float4*)&A[(size_t)(row0 + ar) * K + k0 + kq];
            As[kq + 0][ar] = v.x; As[kq + 1][ar] = v.y;
            As[kq + 2][ar] = v.z; As[kq + 3][ar] = v.w;
        }
#pragma unroll
        for (int i = 0; i < (BK * BN) / 1024; i++) {
            int idx = tid + i * 256;
            int br = idx / (BN / 4), bc = (idx % (BN / 4)) * 4;
            *(float4*)&Bs[br][bc] = *(const float4*)&B[(size_t)(k0 + br) * N + col0 + bc];
        }
        __syncthreads();
#pragma unroll
        for (int kk = 0; kk < BK; kk++) {
            float a[TM], b[TN];
            *(float4*)&a[0] = *(float4*)&As[kk][ty * 8];
            *(float4*)&a[4] = *(float4*)&As[kk][ty * 8 + 4];
            *(float4*)&b[0] = *(float4*)&Bs[kk][tx * TN];
            if (TN == 8) *(float4*)&b[4] = *(float4*)&Bs[kk][tx * TN + 4];
#pragma unroll
            for (int r = 0; r < TM; r++)
#pragma unroll
                for (int c = 0; c < TN; c++) acc[r][c] += a[r] * b[c];
        }
        __syncthreads();
    }
#pragma unroll
    for (int r = 0; r < TM; r++) {
        size_t off = (size_t)(row0 + ty * 8 + r) * N + col0 + tx * TN;
        *(float4*)&C[off] = make_float4(acc[r][0], acc[r][1], acc[r][2], acc[r][3]);
        if (TN == 8)
            *(float4*)&C[off + 4] = make_float4(acc[r][4], acc[r][5], acc[r][6], acc[r][7]);
    }
}

// ================= CSR build =================
__global__ void hist_kernel(const int* __restrict__ rows) {
    int i = blockIdx.x * 256 + threadIdx.x;
    int4 r = ((const int4*)rows)[i];
    atomicAdd(&g_cnt[r.x], 1);
    atomicAdd(&g_cnt[r.y], 1);
    atomicAdd(&g_cnt[r.z], 1);
    atomicAdd(&g_cnt[r.w], 1);
}

__global__ void scan_kernel() {
    __shared__ int s[1024];
    int t = threadIdx.x;
    int loc[8];
    int tot = 0;
#pragma unroll
    for (int j = 0; j < 8; j++) { loc[j] = g_cnt[t * 8 + j]; tot += loc[j]; }
    s[t] = tot;
    __syncthreads();
    for (int off = 1; off < 1024; off <<= 1) {
        int v = (t >= off) ? s[t - off] : 0;
        __syncthreads();
        s[t] += v;
        __syncthreads();
    }
    int base = s[t] - tot;
#pragma unroll
    for (int j = 0; j < 8; j++) { g_rp[t * 8 + j] = base; base += loc[j]; }
    if (t == 1023) g_rp[NN] = s[1023];
}

__global__ void scatter_kernel(const int* __restrict__ rows, const int* __restrict__ cols,
                               const float* __restrict__ vals) {
    int e = blockIdx.x * 256 + threadIdx.x;
    int r = rows[e];
    int pos = g_rp[r] + atomicAdd(&g_cnt[r], 1);
    g_colval[pos] = make_int2(cols[e], __float_as_int(vals[e]));
}

// ================= SpMM D=256 =================
__global__ void spmm256(const float* __restrict__ X, float* __restrict__ Y, int relu) {
    int r = blockIdx.x;
    int t = threadIdx.x;
    int s = g_rp[r], e = g_rp[r + 1];
    float acc = 0.f;
    int i = s;
    for (; i + 4 <= e; i += 4) {
        int2 c0 = g_colval[i], c1 = g_colval[i + 1], c2 = g_colval[i + 2], c3 = g_colval[i + 3];
        acc += __int_as_float(c0.y) * X[(size_t)c0.x * 256 + t];
        acc += __int_as_float(c1.y) * X[(size_t)c1.x * 256 + t];
        acc += __int_as_float(c2.y) * X[(size_t)c2.x * 256 + t];
        acc += __int_as_float(c3.y) * X[(size_t)c3.x * 256 + t];
    }
    for (; i < e; i++) {
        int2 c = g_colval[i];
        acc += __int_as_float(c.y) * X[(size_t)c.x * 256 + t];
    }
    Y[(size_t)r * 256 + t] = relu ? fmaxf(acc, 0.f) : acc;
}

// ================= Wcat =================
__global__ void wcat_kernel(const float* __restrict__ W2, const float* __restrict__ W3,
                            const float* __restrict__ dW) {
    int k = blockIdx.x;
    int c = threadIdx.x;
    const float* Ws = (c < 64) ? W2 : W3;
    int cc = c & 63;
    float a = 0.f;
#pragma unroll 4
    for (int j = 0; j < H2D; j++) a += Ws[k * H2D + j] * dW[j * H3D + cc];
    g_Wcat[k * H2D + c] = a;
}

// ================= epilogue =================
__global__ void epilogue_kernel(const float* __restrict__ db, const float* __restrict__ d1W,
                                const float* __restrict__ d1b,
                                float* __restrict__ mu, float* __restrict__ lv,
                                float* __restrict__ o6) {
    int r = blockIdx.x;
    int t = threadIdx.x;
    float b = db[t];
    float m = g_ml[(size_t)r * 128 + t] + b;
    float l = g_ml[(size_t)r * 128 + 64 + t] + b;
    mu[(size_t)r * 64 + t] = m;
    lv[(size_t)r * 64 + t] = l;
    __shared__ float sm[64];
    sm[t] = m;
    __syncthreads();
    if (t < O6) {
        float a = d1b[t];
#pragma unroll
        for (int k = 0; k < 64; k++) a += sm[k] * d1W[k * O6 + t];
        o6[(size_t)r * O6 + t] = a;
    }
}

// ================= launch =================
extern "C" void kernel_launch(void* const* d_in, const int* in_sizes, int n_in,
                              void* d_out, int out_size) {
    const float* x        = (const float*)d_in[0];
    const int*   adj_rows = (const int*)d_in[1];
    const int*   adj_cols = (const int*)d_in[2];
    const float* adj_vals = (const float*)d_in[3];
    const float* W1       = (const float*)d_in[4];
    const float* W2       = (const float*)d_in[5];
    const float* W3       = (const float*)d_in[6];
    const float* dense_W  = (const float*)d_in[7];
    const float* dense_b  = (const float*)d_in[8];
    const float* dense1_W = (const float*)d_in[9];
    const float* dense1_b = (const float*)d_in[10];

    float* out = (float*)d_out;
    float* adj = out;
    float* o6  = adj + (size_t)NN * NN;
    float* mu  = o6 + (size_t)NN * O6;
    float* lv  = mu + (size_t)NN * H3D;

    void *p_xw1, *p_h1, *p_ah1, *p_ml, *p_wcat, *p_cnt, *p_w1t;
    cudaGetSymbolAddress(&p_xw1, g_xw1);
    cudaGetSymbolAddress(&p_h1, g_h1);
    cudaGetSymbolAddress(&p_ah1, g_ah1);
    cudaGetSymbolAddress(&p_ml, g_ml);
    cudaGetSymbolAddress(&p_wcat, g_Wcat);
    cudaGetSymbolAddress(&p_cnt, g_cnt);
    cudaGetSymbolAddress(&p_w1t, g_w1t);

    // 0) W1T
    transpose_kernel<<<dim3(H1D / 32, FIN / 32), dim3(32, 8)>>>(W1, (float*)p_w1t, FIN, H1D);

    // 1) xw1 = x @ W1 via tensor NT GEMM (M=8192, N=256, K=512)
    mma_nt_kernel<<<dim3(H1D / 128, NN / 128), 256>>>(x, (const float*)p_w1t,
                                                      (float*)p_xw1, FIN, H1D);

    // 2) CSR build
    cudaMemsetAsync(p_cnt, 0, NN * sizeof(int));
    hist_kernel<<<NE / 1024, 256>>>(adj_rows);
    scan_kernel<<<1, 1024>>>();
    cudaMemsetAsync(p_cnt, 0, NN * sizeof(int));
    scatter_kernel<<<NE / 256, 256>>>(adj_rows, adj_cols, adj_vals);

    // 3) h1 = relu(A @ xw1); ah1 = A @ h1
    spmm256<<<NN, 256>>>((const float*)p_xw1, (float*)p_h1, 1);
    spmm256<<<NN, 256>>>((const float*)p_h1, (float*)p_ah1, 0);

    // 4) Wcat; ml = ah1 @ Wcat
    wcat_kernel<<<H1D, H2D>>>(W2, W3, dense_W);
    sgemm_tmpl<64, 4><<<dim3(H2D / 64, NN / 128), 256>>>((const float*)p_ah1, (const float*)p_wcat,
                                                         (float*)p_ml, NN, H2D, H1D);

    // 5) mu / logvar / out6
    epilogue_kernel<<<NN, 64>>>(dense_b, dense1_W, dense1_b, mu, lv, o6);

    // 6) adj_rec = mu @ mu^T (tensor path, symmetric)
    zzt_mma_kernel<<<dim3(NN / 128, NN / 128), 256>>>(mu, adj);
}

// round 4
// speedup vs baseline: 1.3290x; 1.0930x over previous
#include <cuda_runtime.h>

#define NN 8192
#define NE 262144
#define FIN 512
#define H1D 256
#define H2D 128
#define H3D 64
#define O6 6

// ---------------- device scratch ----------------
__device__ float g_xw1[NN * H1D];
__device__ float g_h1[NN * H1D];
__device__ float g_ah1[NN * H1D];
__device__ float g_Wcat[H1D * H2D];
__device__ float g_w1t[H1D * FIN];
__device__ int   g_cnt[NN];          // zero-init; invariant: returns to 0 after scatter
__device__ int   g_rp[NN + 1];
__device__ int2  g_colval[NE];
// fragment packs for zzt (tf32 hi/lo of mu)
__device__ float4 g_Ahi[512 * 8 * 32];
__device__ float4 g_Alo[512 * 8 * 32];
__device__ float2 g_Bhi[1024 * 8 * 32];
__device__ float2 g_Blo[1024 * 8 * 32];

// ---------------- tf32 helpers ----------------
__device__ __forceinline__ void tf32_split(float x, unsigned& hi, unsigned& lo) {
    unsigned h;
    asm("cvt.rna.tf32.f32 %0, %1;" : "=r"(h) : "f"(x));
    float lf = x - __uint_as_float(h);
    unsigned l;
    asm("cvt.rna.tf32.f32 %0, %1;" : "=r"(l) : "f"(lf));
    hi = h; lo = l;
}
__device__ __forceinline__ float tf32_hi_f(float x) {
    unsigned h; asm("cvt.rna.tf32.f32 %0, %1;" : "=r"(h) : "f"(x)); return __uint_as_float(h);
}

__device__ __forceinline__ void mma_tf32(float* c, const unsigned* a, const unsigned* b) {
    asm volatile(
        "mma.sync.aligned.m16n8k8.row.col.f32.tf32.tf32.f32 "
        "{%0,%1,%2,%3}, {%4,%5,%6,%7}, {%8,%9}, {%0,%1,%2,%3};"
        : "+f"(c[0]), "+f"(c[1]), "+f"(c[2]), "+f"(c[3])
        : "r"(a[0]), "r"(a[1]), "r"(a[2]), "r"(a[3]), "r"(b[0]), "r"(b[1]));
}
__device__ __forceinline__ void mma4(float* c, float4 a, float2 b) {
    unsigned ar[4] = {__float_as_uint(a.x), __float_as_uint(a.y),
                      __float_as_uint(a.z), __float_as_uint(a.w)};
    unsigned br[2] = {__float_as_uint(b.x), __float_as_uint(b.y)};
    mma_tf32(c, ar, br);
}

#define SP 20

// ================= NT tensor GEMM for xw1 (unchanged from R3) =================
__global__ void mma_nt_kernel(const float* __restrict__ A, const float* __restrict__ Bt,
                              float* __restrict__ C, int K, int N) {
    __shared__ float buf[4 * 128 * SP];
    float* As_hi = buf;
    float* As_lo = buf + 128 * SP;
    float* Bs_hi = buf + 2 * 128 * SP;
    float* Bs_lo = buf + 3 * 128 * SP;
    int tid = threadIdx.x;
    int lane = tid & 31, warp = tid >> 5;
    int wr = warp >> 2, wc = warp & 3;
    int lr = lane >> 2, lc = lane & 3;
    int i0 = blockIdx.y * 128, j0 = blockIdx.x * 128;
    float acc[4][4][4];
#pragma unroll
    for (int m = 0; m < 4; m++)
#pragma unroll
        for (int n = 0; n < 4; n++)
#pragma unroll
            for (int q = 0; q < 4; q++) acc[m][n][q] = 0.f;

    for (int kc = 0; kc < K; kc += 16) {
#pragma unroll
        for (int i = 0; i < 2; i++) {
            int idx = tid + i * 256;
            int r = idx >> 2, kq = (idx & 3) * 4;
            float4 va = *(const float4*)&A[(size_t)(i0 + r) * K + kc + kq];
            float4 vb = *(const float4*)&Bt[(size_t)(j0 + r) * K + kc + kq];
            unsigned h, l;
            tf32_split(va.x, h, l); As_hi[r * SP + kq + 0] = __uint_as_float(h); As_lo[r * SP + kq + 0] = __uint_as_float(l);
            tf32_split(va.y, h, l); As_hi[r * SP + kq + 1] = __uint_as_float(h); As_lo[r * SP + kq + 1] = __uint_as_float(l);
            tf32_split(va.z, h, l); As_hi[r * SP + kq + 2] = __uint_as_float(h); As_lo[r * SP + kq + 2] = __uint_as_float(l);
            tf32_split(va.w, h, l); As_hi[r * SP + kq + 3] = __uint_as_float(h); As_lo[r * SP + kq + 3] = __uint_as_float(l);
            tf32_split(vb.x, h, l); Bs_hi[r * SP + kq + 0] = __uint_as_float(h); Bs_lo[r * SP + kq + 0] = __uint_as_float(l);
            tf32_split(vb.y, h, l); Bs_hi[r * SP + kq + 1] = __uint_as_float(h); Bs_lo[r * SP + kq + 1] = __uint_as_float(l);
            tf32_split(vb.z, h, l); Bs_hi[r * SP + kq + 2] = __uint_as_float(h); Bs_lo[r * SP + kq + 2] = __uint_as_float(l);
            tf32_split(vb.w, h, l); Bs_hi[r * SP + kq + 3] = __uint_as_float(h); Bs_lo[r * SP + kq + 3] = __uint_as_float(l);
        }
        __syncthreads();
#pragma unroll
        for (int ks = 0; ks < 2; ks++) {
            int kb = ks * 8 + lc;
            unsigned a_hi[4][4], a_lo[4][4], b_hi[4][2], b_lo[4][2];
#pragma unroll
            for (int mf = 0; mf < 4; mf++) {
                int r0 = wr * 64 + mf * 16 + lr;
                a_hi[mf][0] = __float_as_uint(As_hi[r0 * SP + kb]);
                a_hi[mf][1] = __float_as_uint(As_hi[(r0 + 8) * SP + kb]);
                a_hi[mf][2] = __float_as_uint(As_hi[r0 * SP + kb + 4]);
                a_hi[mf][3] = __float_as_uint(As_hi[(r0 + 8) * SP + kb + 4]);
                a_lo[mf][0] = __float_as_uint(As_lo[r0 * SP + kb]);
                a_lo[mf][1] = __float_as_uint(As_lo[(r0 + 8) * SP + kb]);
                a_lo[mf][2] = __float_as_uint(As_lo[r0 * SP + kb + 4]);
                a_lo[mf][3] = __float_as_uint(As_lo[(r0 + 8) * SP + kb + 4]);
            }
#pragma unroll
            for (int nf = 0; nf < 4; nf++) {
                int n0 = wc * 32 + nf * 8 + lr;
                b_hi[nf][0] = __float_as_uint(Bs_hi[n0 * SP + kb]);
                b_hi[nf][1] = __float_as_uint(Bs_hi[n0 * SP + kb + 4]);
                b_lo[nf][0] = __float_as_uint(Bs_lo[n0 * SP + kb]);
                b_lo[nf][1] = __float_as_uint(Bs_lo[n0 * SP + kb + 4]);
            }
#pragma unroll
            for (int mf = 0; mf < 4; mf++)
#pragma unroll
                for (int nf = 0; nf < 4; nf++) {
                    mma_tf32(acc[mf][nf], a_hi[mf], b_hi[nf]);
                    mma_tf32(acc[mf][nf], a_hi[mf], b_lo[nf]);
                    mma_tf32(acc[mf][nf], a_lo[mf], b_hi[nf]);
                }
        }
        __syncthreads();
    }
#pragma unroll
    for (int mf = 0; mf < 4; mf++) {
        int r = i0 + wr * 64 + mf * 16 + lr;
#pragma unroll
        for (int nf = 0; nf < 4; nf++) {
            int j = j0 + wc * 32 + nf * 8 + 2 * lc;
            *(float2*)&C[(size_t)r * N + j] = make_float2(acc[mf][nf][0], acc[mf][nf][1]);
            *(float2*)&C[(size_t)(r + 8) * N + j] = make_float2(acc[mf][nf][2], acc[mf][nf][3]);
        }
    }
}

// ================= transpose W1 =================
__global__ void transpose_kernel(const float* __restrict__ W, float* __restrict__ WT,
                                 int R, int Ccols) {
    __shared__ float t[32][33];
    int c0 = blockIdx.x * 32, r0 = blockIdx.y * 32;
    int x = threadIdx.x, y = threadIdx.y;
#pragma unroll
    for (int i = 0; i < 32; i += 8) t[y + i][x] = W[(size_t)(r0 + y + i) * Ccols + c0 + x];
    __syncthreads();
#pragma unroll
    for (int i = 0; i < 32; i += 8) WT[(size_t)(c0 + y + i) * R + r0 + x] = t[x][y + i];
}

// ================= CSR build =================
__global__ void hist_kernel(const int* __restrict__ rows) {
    int i = blockIdx.x * 256 + threadIdx.x;
    int4 r = ((const int4*)rows)[i];
    atomicAdd(&g_cnt[r.x], 1);
    atomicAdd(&g_cnt[r.y], 1);
    atomicAdd(&g_cnt[r.z], 1);
    atomicAdd(&g_cnt[r.w], 1);
}

// shfl-based scan: 1024 threads x 8 elems, 2 barriers
__global__ void scan_kernel() {
    __shared__ int wtot[32];
    __shared__ int wexc[32];
    int t = threadIdx.x;
    int lane = t & 31, warp = t >> 5;
    int4 a = ((const int4*)g_cnt)[t * 2];
    int4 b = ((const int4*)g_cnt)[t * 2 + 1];
    int s8 = a.x + a.y + a.z + a.w + b.x + b.y + b.z + b.w;
    // warp inclusive scan of s8
    int inc = s8;
#pragma unroll
    for (int d = 1; d < 32; d <<= 1) {
        int v = __shfl_up_sync(0xffffffff, inc, d);
        if (lane >= d) inc += v;
    }
    if (lane == 31) wtot[warp] = inc;
    __syncthreads();
    if (warp == 0) {
        int v = wtot[lane];
        int wi = v;
#pragma unroll
        for (int d = 1; d < 32; d <<= 1) {
            int u = __shfl_up_sync(0xffffffff, wi, d);
            if (lane >= d) wi += u;
        }
        wexc[lane] = wi - v;
        if (lane == 31) g_rp[NN] = wi;
    }
    __syncthreads();
    int base = wexc[warp] + inc - s8;   // exclusive prefix for this thread's 8
    int o = base;
    g_rp[t * 8 + 0] = o; o += a.x;
    g_rp[t * 8 + 1] = o; o += a.y;
    g_rp[t * 8 + 2] = o; o += a.z;
    g_rp[t * 8 + 3] = o; o += a.w;
    g_rp[t * 8 + 4] = o; o += b.x;
    g_rp[t * 8 + 5] = o; o += b.y;
    g_rp[t * 8 + 6] = o; o += b.z;
    g_rp[t * 8 + 7] = o;
}

// scatter with atomicSub: cnt returns to 0 afterwards (replay-safe, no memset)
__global__ void scatter_kernel(const int* __restrict__ rows, const int* __restrict__ cols,
                               const float* __restrict__ vals) {
    int e = blockIdx.x * 256 + threadIdx.x;
    int r = rows[e];
    int old = atomicSub(&g_cnt[r], 1);
    int pos = g_rp[r] + old - 1;
    g_colval[pos] = make_int2(cols[e], __float_as_int(vals[e]));
}

// ================= SpMM: float4, 64 threads/row, 4 rows/block =================
__global__ void spmm_v4(const float* __restrict__ X, float* __restrict__ Y, int relu) {
    int r = blockIdx.x * 4 + (threadIdx.x >> 6);
    int t = threadIdx.x & 63;
    int s = g_rp[r], e = g_rp[r + 1];
    const float4* X4 = (const float4*)X;
    float4 acc = make_float4(0.f, 0.f, 0.f, 0.f);
    int i = s;
    for (; i + 4 <= e; i += 4) {
        int2 c0 = g_colval[i], c1 = g_colval[i + 1], c2 = g_colval[i + 2], c3 = g_colval[i + 3];
        float4 x0 = X4[(size_t)c0.x * 64 + t];
        float4 x1 = X4[(size_t)c1.x * 64 + t];
        float4 x2 = X4[(size_t)c2.x * 64 + t];
        float4 x3 = X4[(size_t)c3.x * 64 + t];
        float v0 = __int_as_float(c0.y), v1 = __int_as_float(c1.y);
        float v2 = __int_as_float(c2.y), v3 = __int_as_float(c3.y);
        acc.x += v0 * x0.x + v1 * x1.x + v2 * x2.x + v3 * x3.x;
        acc.y += v0 * x0.y + v1 * x1.y + v2 * x2.y + v3 * x3.y;
        acc.z += v0 * x0.z + v1 * x1.z + v2 * x2.z + v3 * x3.z;
        acc.w += v0 * x0.w + v1 * x1.w + v2 * x2.w + v3 * x3.w;
    }
    for (; i < e; i++) {
        int2 c = g_colval[i];
        float4 xv = X4[(size_t)c.x * 64 + t];
        float v = __int_as_float(c.y);
        acc.x += v * xv.x; acc.y += v * xv.y; acc.z += v * xv.z; acc.w += v * xv.w;
    }
    if (relu) {
        acc.x = fmaxf(acc.x, 0.f); acc.y = fmaxf(acc.y, 0.f);
        acc.z = fmaxf(acc.z, 0.f); acc.w = fmaxf(acc.w, 0.f);
    }
    ((float4*)Y)[(size_t)r * 64 + t] = acc;
}

// ================= Wcat = [W2@dense_W | W3@dense_W] =================
__global__ void wcat_kernel(const float* __restrict__ W2, const float* __restrict__ W3,
                            const float* __restrict__ dW) {
    int k = blockIdx.x;
    int c = threadIdx.x;
    const float* Ws = (c < 64) ? W2 : W3;
    int cc = c & 63;
    float a = 0.f;
#pragma unroll 4
    for (int j = 0; j < H2D; j++) a += Ws[k * H2D + j] * dW[j * H3D + cc];
    g_Wcat[k * H2D + c] = a;
}

// ================= fused ml GEMM: mu/lv = ah1 @ Wcat + bias, direct split outputs ===========
__global__ void ml_kernel(const float* __restrict__ A, const float* __restrict__ db,
                          float* __restrict__ mu, float* __restrict__ lv) {
    const int BK = 16;
    __shared__ float As[BK][132];
    __shared__ float Bs[BK][132];
    int tid = threadIdx.x;
    int tx = tid & 15, ty = tid >> 4;
    int row0 = blockIdx.x * 128;
    float acc[8][8];
#pragma unroll
    for (int r = 0; r < 8; r++)
#pragma unroll
        for (int c = 0; c < 8; c++) acc[r][c] = 0.f;
    for (int k0 = 0; k0 < H1D; k0 += BK) {
#pragma unroll
        for (int i = 0; i < 2; i++) {
            int idx = tid + i * 256;
            int ar = idx >> 2, kq = (idx & 3) * 4;
            float4 v = *(const float4*)&A[(size_t)(row0 + ar) * H1D + k0 + kq];
            As[kq + 0][ar] = v.x; As[kq + 1][ar] = v.y;
            As[kq + 2][ar] = v.z; As[kq + 3][ar] = v.w;
        }
        {
            int br = tid >> 5, bc = (tid & 31) * 4;
            *(float4*)&Bs[br][bc] = *(const float4*)&g_Wcat[(k0 + br) * H2D + bc];
            *(float4*)&Bs[br + 8][bc] = *(const float4*)&g_Wcat[(k0 + br + 8) * H2D + bc];
        }
        __syncthreads();
#pragma unroll
        for (int kk = 0; kk < BK; kk++) {
            float a[8], b[8];
            *(float4*)&a[0] = *(float4*)&As[kk][ty * 8];
            *(float4*)&a[4] = *(float4*)&As[kk][ty * 8 + 4];
            *(float4*)&b[0] = *(float4*)&Bs[kk][tx * 8];
            *(float4*)&b[4] = *(float4*)&Bs[kk][tx * 8 + 4];
#pragma unroll
            for (int r = 0; r < 8; r++)
#pragma unroll
                for (int c = 0; c < 8; c++) acc[r][c] += a[r] * b[c];
        }
        __syncthreads();
    }
    int colg = tx * 8;               // 0..120
    float bias[8];
#pragma unroll
    for (int c = 0; c < 8; c++) bias[c] = __ldg(&db[(colg + c) & 63]);
    float* dst = (colg < 64) ? mu : lv;
    int cc = colg & 63;
#pragma unroll
    for (int r = 0; r < 8; r++) {
        int rg = row0 + ty * 8 + r;
        float4 v0 = make_float4(acc[r][0] + bias[0], acc[r][1] + bias[1],
                                acc[r][2] + bias[2], acc[r][3] + bias[3]);
        float4 v1 = make_float4(acc[r][4] + bias[4], acc[r][5] + bias[5],
                                acc[r][6] + bias[6], acc[r][7] + bias[7]);
        *(float4*)&dst[(size_t)rg * 64 + cc] = v0;
        *(float4*)&dst[(size_t)rg * 64 + cc + 4] = v1;
    }
}

// ================= pack mu into tf32 fragment layout for zzt =================
__global__ void pack_kernel(const float* __restrict__ mu) {
    int t = threadIdx.x;
    int lane = t & 31, ks = t >> 5;          // ks 0..7
    int g = blockIdx.x;                      // 0..511
    int lr = lane >> 2, lc = lane & 3;
    int k = ks * 8 + lc;
    // A pack: rows g*16+lr, g*16+lr+8, cols k, k+4
    float v0 = mu[(size_t)(g * 16 + lr) * 64 + k];
    float v1 = mu[(size_t)(g * 16 + lr + 8) * 64 + k];
    float v2 = mu[(size_t)(g * 16 + lr) * 64 + k + 4];
    float v3 = mu[(size_t)(g * 16 + lr + 8) * 64 + k + 4];
    unsigned h0, l0, h1, l1, h2, l2, h3, l3;
    tf32_split(v0, h0, l0); tf32_split(v1, h1, l1);
    tf32_split(v2, h2, l2); tf32_split(v3, h3, l3);
    int ia = (g * 8 + ks) * 32 + lane;
    g_Ahi[ia] = make_float4(__uint_as_float(h0), __uint_as_float(h1),
                            __uint_as_float(h2), __uint_as_float(h3));
    g_Alo[ia] = make_float4(__uint_as_float(l0), __uint_as_float(l1),
                            __uint_as_float(l2), __uint_as_float(l3));
    // B packs: two 8-row groups per block (2g, 2g+1); n = gb*8 + lr, k rows = lc, lc+4
#pragma unroll
    for (int q = 0; q < 2; q++) {
        int gb = 2 * g + q;
        float b0 = mu[(size_t)(gb * 8 + lr) * 64 + k];
        float b1 = mu[(size_t)(gb * 8 + lr) * 64 + k + 4];
        unsigned bh0, bl0, bh1, bl1;
        tf32_split(b0, bh0, bl0); tf32_split(b1, bh1, bl1);
        int ib = (gb * 8 + ks) * 32 + lane;
        g_Bhi[ib] = make_float2(__uint_as_float(bh0), __uint_as_float(bh1));
        g_Blo[ib] = make_float2(__uint_as_float(bl0), __uint_as_float(bl1));
    }
}

// ================= out6 = mu @ d1W + d1b =================
__global__ void o6_kernel(const float* __restrict__ mu, const float* __restrict__ d1W,
                          const float* __restrict__ d1b, float* __restrict__ o6) {
    __shared__ float w[64 * O6];
    int t = threadIdx.x;                     // 0..383
    if (t < 64 * O6) w[t] = d1W[t];
    __syncthreads();
    int rl = t / O6, c = t - rl * O6;        // 64 rows x 6
    int row = blockIdx.x * 64 + rl;
    float a = d1b[c];
    const float* mr = &mu[(size_t)row * 64];
#pragma unroll 8
    for (int k = 0; k < 64; k++) a += mr[k] * w[k * O6 + c];
    o6[(size_t)row * O6 + c] = a;
}

// ================= zzt from packs: no smem mainloop, no syncthreads =================
__global__ void __launch_bounds__(256) zzt_pack_kernel(float* __restrict__ C) {
    int bx = blockIdx.x, by = blockIdx.y;
    if (by > bx) return;
    __shared__ float T[32][132];
    int tid = threadIdx.x;
    int lane = tid & 31, warp = tid >> 5;
    int wr = warp >> 2, wc = warp & 3;
    int lr = lane >> 2, lc = lane & 3;
    int i0 = by * 128, j0 = bx * 128;
    int ga0 = by * 8 + wr * 4;
    int gb0 = bx * 16 + wc * 4;

    float acc[4][4][4];
#pragma unroll
    for (int m = 0; m < 4; m++)
#pragma unroll
        for (int n = 0; n < 4; n++)
#pragma unroll
            for (int q = 0; q < 4; q++) acc[m][n][q] = 0.f;

#pragma unroll 2
    for (int ks = 0; ks < 8; ks++) {
        float4 ah[4], al[4];
        float2 bh[4], bl[4];
#pragma unroll
        for (int mf = 0; mf < 4; mf++) {
            int ia = ((ga0 + mf) * 8 + ks) * 32 + lane;
            ah[mf] = g_Ahi[ia];
            al[mf] = g_Alo[ia];
        }
#pragma unroll
        for (int nf = 0; nf < 4; nf++) {
            int ib = ((gb0 + nf) * 8 + ks) * 32 + lane;
            bh[nf] = g_Bhi[ib];
            bl[nf] = g_Blo[ib];
        }
#pragma unroll
        for (int mf = 0; mf < 4; mf++)
#pragma unroll
            for (int nf = 0; nf < 4; nf++) {
                mma4(acc[mf][nf], ah[mf], bh[nf]);
                mma4(acc[mf][nf], ah[mf], bl[nf]);
                mma4(acc[mf][nf], al[mf], bh[nf]);
            }
    }
    // direct tile
#pragma unroll
    for (int mf = 0; mf < 4; mf++) {
        int r = i0 + wr * 64 + mf * 16 + lr;
#pragma unroll
        for (int nf = 0; nf < 4; nf++) {
            int j = j0 + wc * 32 + nf * 8 + 2 * lc;
            *(float2*)&C[(size_t)r * NN + j] = make_float2(acc[mf][nf][0], acc[mf][nf][1]);
            *(float2*)&C[(size_t)(r + 8) * NN + j] = make_float2(acc[mf][nf][2], acc[mf][nf][3]);
        }
    }
    if (bx == by) return;
    // mirror via smem transpose, 4 strips of 32 cols
#pragma unroll
    for (int s = 0; s < 4; s++) {
        __syncthreads();
        if (wc == s) {
#pragma unroll
            for (int mf = 0; mf < 4; mf++) {
                int rl = wr * 64 + mf * 16 + lr;
#pragma unroll
                for (int nf = 0; nf < 4; nf++) {
                    int cl = nf * 8 + 2 * lc;
                    T[cl][rl] = acc[mf][nf][0];
                    T[cl + 1][rl] = acc[mf][nf][1];
                    T[cl][rl + 8] = acc[mf][nf][2];
                    T[cl + 1][rl + 8] = acc[mf][nf][3];
                }
            }
        }
        __syncthreads();
        int jj = tid >> 3, seg = (tid & 7) * 16;
        size_t base = (size_t)(j0 + s * 32 + jj) * NN + i0 + seg;
#pragma unroll
        for (int q = 0; q < 4; q++)
            *(float4*)&C[base + q * 4] = *(float4*)&T[jj][seg + q * 4];
    }
}

// ================= launch =================
extern "C" void kernel_launch(void* const* d_in, const int* in_sizes, int n_in,
                              void* d_out, int out_size) {
    const float* x        = (const float*)d_in[0];
    const int*   adj_rows = (const int*)d_in[1];
    const int*   adj_cols = (const int*)d_in[2];
    const float* adj_vals = (const float*)d_in[3];
    const float* W1       = (const float*)d_in[4];
    const float* W2       = (const float*)d_in[5];
    const float* W3       = (const float*)d_in[6];
    const float* dense_W  = (const float*)d_in[7];
    const float* dense_b  = (const float*)d_in[8];
    const float* dense1_W = (const float*)d_in[9];
    const float* dense1_b = (const float*)d_in[10];

    float* out = (float*)d_out;
    float* adj = out;
    float* o6  = adj + (size_t)NN * NN;
    float* mu  = o6 + (size_t)NN * O6;
    float* lv  = mu + (size_t)NN * H3D;

    void *p_xw1, *p_h1, *p_ah1, *p_w1t;
    cudaGetSymbolAddress(&p_xw1, g_xw1);
    cudaGetSymbolAddress(&p_h1, g_h1);
    cudaGetSymbolAddress(&p_ah1, g_ah1);
    cudaGetSymbolAddress(&p_w1t, g_w1t);

    // small prep
    wcat_kernel<<<H1D, H2D>>>(W2, W3, dense_W);
    transpose_kernel<<<dim3(H1D / 32, FIN / 32), dim3(32, 8)>>>(W1, (float*)p_w1t, FIN, H1D);

    // xw1 = x @ W1 (tensor NT)
    mma_nt_kernel<<<dim3(H1D / 128, NN / 128), 256>>>(x, (const float*)p_w1t,
                                                      (float*)p_xw1, FIN, H1D);

    // CSR (no memsets: g_cnt invariant 0)
    hist_kernel<<<NE / 1024, 256>>>(adj_rows);
    scan_kernel<<<1, 1024>>>();
    scatter_kernel<<<NE / 256, 256>>>(adj_rows, adj_cols, adj_vals);

    // SpMMs
    spmm_v4<<<NN / 4, 256>>>((const float*)p_xw1, (float*)p_h1, 1);
    spmm_v4<<<NN / 4, 256>>>((const float*)p_h1, (float*)p_ah1, 0);

    // mu/lv fused GEMM
    ml_kernel<<<NN / 128, 256>>>((const float*)p_ah1, dense_b, mu, lv);

    // pack + o6
    pack_kernel<<<512, 256>>>(mu);
    o6_kernel<<<NN / 64, 384>>>(mu, dense1_W, dense1_b, o6);

    // adj_rec
    zzt_pack_kernel<<<dim3(NN / 128, NN / 128), 256>>>(adj);
}

// round 5
// speedup vs baseline: 1.8348x; 1.3806x over previous
#include <cuda_runtime.h>
#include <cuda_bf16.h>

#define NN 8192
#define NE 262144
#define FIN 512
#define H1D 256
#define H2D 128
#define H3D 64
#define O6 6

// ---------------- device scratch ----------------
__device__ float g_xw1[NN * H1D];
__device__ float g_h1[NN * H1D];
__device__ float g_ah1[NN * H1D];
__device__ float g_Wcat[H1D * H2D];
__device__ int   g_cnt[NN];          // zero-init; invariant: returns to 0 after scatter
__device__ int   g_rp[NN + 1];
__device__ int2  g_colval[NE];
// bf16 fragment packs: x (A of xw1), W1 (B of xw1), mu (A and B of zzt)
__device__ uint4 g_XAh[512 * 32 * 32];   // 8 MB
__device__ uint4 g_XAl[512 * 32 * 32];
__device__ uint2 g_WBh[32 * 32 * 32];    // 256 KB
__device__ uint2 g_WBl[32 * 32 * 32];
__device__ uint4 g_MAh[512 * 4 * 32];    // 1 MB
__device__ uint4 g_MAl[512 * 4 * 32];
__device__ uint2 g_MBh[1024 * 4 * 32];   // 1 MB
__device__ uint2 g_MBl[1024 * 4 * 32];

// ---------------- bf16 split helpers ----------------
__device__ __forceinline__ void bsplit2(float x0, float x1, unsigned& hp, unsigned& lp) {
    __nv_bfloat16 h0 = __float2bfloat16(x0), h1 = __float2bfloat16(x1);
    float r0 = x0 - __bfloat162float(h0), r1 = x1 - __bfloat162float(h1);
    __nv_bfloat16 l0 = __float2bfloat16(r0), l1 = __float2bfloat16(r1);
    hp = (unsigned)__bfloat16_as_ushort(h0) | ((unsigned)__bfloat16_as_ushort(h1) << 16);
    lp = (unsigned)__bfloat16_as_ushort(l0) | ((unsigned)__bfloat16_as_ushort(l1) << 16);
}

__device__ __forceinline__ void mma_bf16(float* c, const unsigned* a, const unsigned* b) {
    asm volatile(
        "mma.sync.aligned.m16n8k16.row.col.f32.bf16.bf16.f32 "
        "{%0,%1,%2,%3}, {%4,%5,%6,%7}, {%8,%9}, {%0,%1,%2,%3};"
        : "+f"(c[0]), "+f"(c[1]), "+f"(c[2]), "+f"(c[3])
        : "r"(a[0]), "r"(a[1]), "r"(a[2]), "r"(a[3]), "r"(b[0]), "r"(b[1]));
}
__device__ __forceinline__ void mma3(float* c, const uint4& ah, const uint4& al,
                                     const uint2& bh, const uint2& bl) {
    unsigned A[4] = {ah.x, ah.y, ah.z, ah.w};
    unsigned Al[4] = {al.x, al.y, al.z, al.w};
    unsigned B[2] = {bh.x, bh.y};
    unsigned Bl[2] = {bl.x, bl.y};
    mma_bf16(c, A, B);
    mma_bf16(c, A, Bl);
    mma_bf16(c, Al, B);
}

// ================= pack x into A-frag layout (512 groups x 32 ksteps) =================
__global__ void pack_x_kernel(const float* __restrict__ x) {
    int g = blockIdx.x;
    int lane = threadIdx.x & 31, ks = threadIdx.x >> 5;   // 32 warps = 32 ksteps
    int lr = lane >> 2, lc = lane & 3;
    int row0 = g * 16 + lr, k0 = ks * 16, c0 = k0 + 2 * lc;
    float2 v0 = *(const float2*)&x[(size_t)row0 * FIN + c0];
    float2 v1 = *(const float2*)&x[(size_t)(row0 + 8) * FIN + c0];
    float2 v2 = *(const float2*)&x[(size_t)row0 * FIN + c0 + 8];
    float2 v3 = *(const float2*)&x[(size_t)(row0 + 8) * FIN + c0 + 8];
    uint4 h, l;
    bsplit2(v0.x, v0.y, h.x, l.x);
    bsplit2(v1.x, v1.y, h.y, l.y);
    bsplit2(v2.x, v2.y, h.z, l.z);
    bsplit2(v3.x, v3.y, h.w, l.w);
    int idx = (g * 32 + ks) * 32 + lane;
    g_XAh[idx] = h;
    g_XAl[idx] = l;
}

// ================= pack W1 into B-frag layout (32 n-groups x 32 ksteps) =================
__global__ void pack_w1_kernel(const float* __restrict__ W1) {
    int gb = blockIdx.x;
    int lane = threadIdx.x & 31, ks = threadIdx.x >> 5;
    int lr = lane >> 2, lc = lane & 3;
    int n0 = gb * 8 + lr, k0 = ks * 16, kc = k0 + 2 * lc;
    float b00 = W1[(size_t)kc * H1D + n0];
    float b01 = W1[(size_t)(kc + 1) * H1D + n0];
    float b10 = W1[(size_t)(kc + 8) * H1D + n0];
    float b11 = W1[(size_t)(kc + 9) * H1D + n0];
    uint2 h, l;
    bsplit2(b00, b01, h.x, l.x);
    bsplit2(b10, b11, h.y, l.y);
    int idx = (gb * 32 + ks) * 32 + lane;
    g_WBh[idx] = h;
    g_WBl[idx] = l;
}

// ================= xw1 = x @ W1, pure-fragment bf16 GEMM =================
// grid (2, 64), 256 threads, 8 warps (wr 0..1, wc 0..3), warp tile 64x32
__global__ void __launch_bounds__(256) xw1_mma_kernel(float* __restrict__ C) {
    int tid = threadIdx.x;
    int lane = tid & 31, warp = tid >> 5;
    int wr = warp >> 2, wc = warp & 3;
    int lr = lane >> 2, lc = lane & 3;
    int ga0 = blockIdx.y * 8 + wr * 4;
    int gb0 = blockIdx.x * 16 + wc * 4;

    float acc[4][4][4];
#pragma unroll
    for (int m = 0; m < 4; m++)
#pragma unroll
        for (int n = 0; n < 4; n++)
#pragma unroll
            for (int q = 0; q < 4; q++) acc[m][n][q] = 0.f;

    for (int ks = 0; ks < 32; ks++) {
        uint4 ah[4], al[4];
#pragma unroll
        for (int mf = 0; mf < 4; mf++) {
            int ia = ((ga0 + mf) * 32 + ks) * 32 + lane;
            ah[mf] = g_XAh[ia];
            al[mf] = g_XAl[ia];
        }
#pragma unroll
        for (int nf = 0; nf < 4; nf++) {
            int ib = ((gb0 + nf) * 32 + ks) * 32 + lane;
            uint2 bh = g_WBh[ib], bl = g_WBl[ib];
#pragma unroll
            for (int mf = 0; mf < 4; mf++) mma3(acc[mf][nf], ah[mf], al[mf], bh, bl);
        }
    }
#pragma unroll
    for (int mf = 0; mf < 4; mf++) {
        int r = blockIdx.y * 128 + wr * 64 + mf * 16 + lr;
#pragma unroll
        for (int nf = 0; nf < 4; nf++) {
            int j = blockIdx.x * 128 + wc * 32 + nf * 8 + 2 * lc;
            *(float2*)&C[(size_t)r * H1D + j] = make_float2(acc[mf][nf][0], acc[mf][nf][1]);
            *(float2*)&C[(size_t)(r + 8) * H1D + j] = make_float2(acc[mf][nf][2], acc[mf][nf][3]);
        }
    }
}

// ================= CSR build =================
__global__ void hist_kernel(const int* __restrict__ rows) {
    int i = blockIdx.x * 256 + threadIdx.x;
    int4 r = ((const int4*)rows)[i];
    atomicAdd(&g_cnt[r.x], 1);
    atomicAdd(&g_cnt[r.y], 1);
    atomicAdd(&g_cnt[r.z], 1);
    atomicAdd(&g_cnt[r.w], 1);
}

__global__ void scan_kernel() {
    __shared__ int wtot[32];
    __shared__ int wexc[32];
    int t = threadIdx.x;
    int lane = t & 31, warp = t >> 5;
    int4 a = ((const int4*)g_cnt)[t * 2];
    int4 b = ((const int4*)g_cnt)[t * 2 + 1];
    int s8 = a.x + a.y + a.z + a.w + b.x + b.y + b.z + b.w;
    int inc = s8;
#pragma unroll
    for (int d = 1; d < 32; d <<= 1) {
        int v = __shfl_up_sync(0xffffffff, inc, d);
        if (lane >= d) inc += v;
    }
    if (lane == 31) wtot[warp] = inc;
    __syncthreads();
    if (warp == 0) {
        int v = wtot[lane];
        int wi = v;
#pragma unroll
        for (int d = 1; d < 32; d <<= 1) {
            int u = __shfl_up_sync(0xffffffff, wi, d);
            if (lane >= d) wi += u;
        }
        wexc[lane] = wi - v;
        if (lane == 31) g_rp[NN] = wi;
    }
    __syncthreads();
    int base = wexc[warp] + inc - s8;
    int o = base;
    g_rp[t * 8 + 0] = o; o += a.x;
    g_rp[t * 8 + 1] = o; o += a.y;
    g_rp[t * 8 + 2] = o; o += a.z;
    g_rp[t * 8 + 3] = o; o += a.w;
    g_rp[t * 8 + 4] = o; o += b.x;
    g_rp[t * 8 + 5] = o; o += b.y;
    g_rp[t * 8 + 6] = o; o += b.z;
    g_rp[t * 8 + 7] = o;
}

__global__ void scatter_kernel(const int* __restrict__ rows, const int* __restrict__ cols,
                               const float* __restrict__ vals) {
    int e = blockIdx.x * 256 + threadIdx.x;
    int r = rows[e];
    int old = atomicSub(&g_cnt[r], 1);
    int pos = g_rp[r] + old - 1;
    g_colval[pos] = make_int2(cols[e], __float_as_int(vals[e]));
}

// ================= SpMM: float4, 64 threads/row, 4 rows/block =================
__global__ void spmm_v4(const float* __restrict__ X, float* __restrict__ Y, int relu) {
    int r = blockIdx.x * 4 + (threadIdx.x >> 6);
    int t = threadIdx.x & 63;
    int s = g_rp[r], e = g_rp[r + 1];
    const float4* X4 = (const float4*)X;
    float4 acc = make_float4(0.f, 0.f, 0.f, 0.f);
    int i = s;
    for (; i + 4 <= e; i += 4) {
        int2 c0 = g_colval[i], c1 = g_colval[i + 1], c2 = g_colval[i + 2], c3 = g_colval[i + 3];
        float4 x0 = X4[(size_t)c0.x * 64 + t];
        float4 x1 = X4[(size_t)c1.x * 64 + t];
        float4 x2 = X4[(size_t)c2.x * 64 + t];
        float4 x3 = X4[(size_t)c3.x * 64 + t];
        float v0 = __int_as_float(c0.y), v1 = __int_as_float(c1.y);
        float v2 = __int_as_float(c2.y), v3 = __int_as_float(c3.y);
        acc.x += v0 * x0.x + v1 * x1.x + v2 * x2.x + v3 * x3.x;
        acc.y += v0 * x0.y + v1 * x1.y + v2 * x2.y + v3 * x3.y;
        acc.z += v0 * x0.z + v1 * x1.z + v2 * x2.z + v3 * x3.z;
        acc.w += v0 * x0.w + v1 * x1.w + v2 * x2.w + v3 * x3.w;
    }
    for (; i < e; i++) {
        int2 c = g_colval[i];
        float4 xv = X4[(size_t)c.x * 64 + t];
        float v = __int_as_float(c.y);
        acc.x += v * xv.x; acc.y += v * xv.y; acc.z += v * xv.z; acc.w += v * xv.w;
    }
    if (relu) {
        acc.x = fmaxf(acc.x, 0.f); acc.y = fmaxf(acc.y, 0.f);
        acc.z = fmaxf(acc.z, 0.f); acc.w = fmaxf(acc.w, 0.f);
    }
    ((float4*)Y)[(size_t)r * 64 + t] = acc;
}

// ================= Wcat = [W2@dense_W | W3@dense_W] =================
__global__ void wcat_kernel(const float* __restrict__ W2, const float* __restrict__ W3,
                            const float* __restrict__ dW) {
    int k = blockIdx.x;
    int c = threadIdx.x;
    const float* Ws = (c < 64) ? W2 : W3;
    int cc = c & 63;
    float a = 0.f;
#pragma unroll 4
    for (int j = 0; j < H2D; j++) a += Ws[k * H2D + j] * dW[j * H3D + cc];
    g_Wcat[k * H2D + c] = a;
}

// ================= fused ml GEMM: mu/lv = ah1 @ Wcat + bias =================
__global__ void ml_kernel(const float* __restrict__ A, const float* __restrict__ db,
                          float* __restrict__ mu, float* __restrict__ lv) {
    const int BK = 16;
    __shared__ float As[BK][132];
    __shared__ float Bs[BK][132];
    int tid = threadIdx.x;
    int tx = tid & 15, ty = tid >> 4;
    int row0 = blockIdx.x * 128;
    float acc[8][8];
#pragma unroll
    for (int r = 0; r < 8; r++)
#pragma unroll
        for (int c = 0; c < 8; c++) acc[r][c] = 0.f;
    for (int k0 = 0; k0 < H1D; k0 += BK) {
#pragma unroll
        for (int i = 0; i < 2; i++) {
            int idx = tid + i * 256;
            int ar = idx >> 2, kq = (idx & 3) * 4;
            float4 v = *(const float4*)&A[(size_t)(row0 + ar) * H1D + k0 + kq];
            As[kq + 0][ar] = v.x; As[kq + 1][ar] = v.y;
            As[kq + 2][ar] = v.z; As[kq + 3][ar] = v.w;
        }
        {
            int br = tid >> 5, bc = (tid & 31) * 4;
            *(float4*)&Bs[br][bc] = *(const float4*)&g_Wcat[(k0 + br) * H2D + bc];
            *(float4*)&Bs[br + 8][bc] = *(const float4*)&g_Wcat[(k0 + br + 8) * H2D + bc];
        }
        __syncthreads();
#pragma unroll
        for (int kk = 0; kk < BK; kk++) {
            float a[8], b[8];
            *(float4*)&a[0] = *(float4*)&As[kk][ty * 8];
            *(float4*)&a[4] = *(float4*)&As[kk][ty * 8 + 4];
            *(float4*)&b[0] = *(float4*)&Bs[kk][tx * 8];
            *(float4*)&b[4] = *(float4*)&Bs[kk][tx * 8 + 4];
#pragma unroll
            for (int r = 0; r < 8; r++)
#pragma unroll
                for (int c = 0; c < 8; c++) acc[r][c] += a[r] * b[c];
        }
        __syncthreads();
    }
    int colg = tx * 8;
    float bias[8];
#pragma unroll
    for (int c = 0; c < 8; c++) bias[c] = __ldg(&db[(colg + c) & 63]);
    float* dst = (colg < 64) ? mu : lv;
    int cc = colg & 63;
#pragma unroll
    for (int r = 0; r < 8; r++) {
        int rg = row0 + ty * 8 + r;
        float4 v0 = make_float4(acc[r][0] + bias[0], acc[r][1] + bias[1],
                                acc[r][2] + bias[2], acc[r][3] + bias[3]);
        float4 v1 = make_float4(acc[r][4] + bias[4], acc[r][5] + bias[5],
                                acc[r][6] + bias[6], acc[r][7] + bias[7]);
        *(float4*)&dst[(size_t)rg * 64 + cc] = v0;
        *(float4*)&dst[(size_t)rg * 64 + cc + 4] = v1;
    }
}

// ================= pack mu into bf16 A/B frag layouts (K=64, 4 ksteps) =================
// grid 512, block 384: warps 0-3 = A ks; warps 4-7 = B group 2g; warps 8-11 = B group 2g+1
__global__ void pack_mu_kernel(const float* __restrict__ mu) {
    int g = blockIdx.x;
    int lane = threadIdx.x & 31, warp = threadIdx.x >> 5;
    int lr = lane >> 2, lc = lane & 3;
    if (warp < 4) {
        int ks = warp, k0 = ks * 16, c0 = k0 + 2 * lc;
        int row0 = g * 16 + lr;
        float2 v0 = *(const float2*)&mu[(size_t)row0 * 64 + c0];
        float2 v1 = *(const float2*)&mu[(size_t)(row0 + 8) * 64 + c0];
        float2 v2 = *(const float2*)&mu[(size_t)row0 * 64 + c0 + 8];
        float2 v3 = *(const float2*)&mu[(size_t)(row0 + 8) * 64 + c0 + 8];
        uint4 h, l;
        bsplit2(v0.x, v0.y, h.x, l.x);
        bsplit2(v1.x, v1.y, h.y, l.y);
        bsplit2(v2.x, v2.y, h.z, l.z);
        bsplit2(v3.x, v3.y, h.w, l.w);
        int idx = (g * 4 + ks) * 32 + lane;
        g_MAh[idx] = h;
        g_MAl[idx] = l;
    } else {
        int q = (warp - 4) >> 2;            // 0 or 1
        int ks = (warp - 4) & 3;
        int gb = 2 * g + q;
        int n0 = gb * 8 + lr, k0 = ks * 16, kc = k0 + 2 * lc;
        float2 b0 = *(const float2*)&mu[(size_t)n0 * 64 + kc];
        float2 b1 = *(const float2*)&mu[(size_t)n0 * 64 + kc + 8];
        uint2 h, l;
        bsplit2(b0.x, b0.y, h.x, l.x);
        bsplit2(b1.x, b1.y, h.y, l.y);
        int idx = (gb * 4 + ks) * 32 + lane;
        g_MBh[idx] = h;
        g_MBl[idx] = l;
    }
}

// ================= out6 = mu @ d1W + d1b =================
__global__ void o6_kernel(const float* __restrict__ mu, const float* __restrict__ d1W,
                          const float* __restrict__ d1b, float* __restrict__ o6) {
    __shared__ float w[64 * O6];
    int t = threadIdx.x;
    if (t < 64 * O6) w[t] = d1W[t];
    __syncthreads();
    int rl = t / O6, c = t - rl * O6;
    int row = blockIdx.x * 64 + rl;
    float a = d1b[c];
    const float* mr = &mu[(size_t)row * 64];
#pragma unroll 8
    for (int k = 0; k < 64; k++) a += mr[k] * w[k * O6 + c];
    o6[(size_t)row * O6 + c] = a;
}

// ================= zzt: bf16 frag packs, 128 threads, warp tile 64x64 =================
__global__ void __launch_bounds__(128) zzt_kernel(float* __restrict__ C) {
    int bx = blockIdx.x, by = blockIdx.y;
    if (by > bx) return;
    __shared__ float T[32][132];
    int tid = threadIdx.x;
    int lane = tid & 31, warp = tid >> 5;
    int wr = warp >> 1, wc = warp & 1;
    int lr = lane >> 2, lc = lane & 3;
    int i0 = by * 128, j0 = bx * 128;
    int ga0 = by * 8 + wr * 4;
    int gb0 = bx * 16 + wc * 8;

    float acc[4][8][4];
#pragma unroll
    for (int m = 0; m < 4; m++)
#pragma unroll
        for (int n = 0; n < 8; n++)
#pragma unroll
            for (int q = 0; q < 4; q++) acc[m][n][q] = 0.f;

#pragma unroll
    for (int ks = 0; ks < 4; ks++) {
        uint4 ah[4], al[4];
#pragma unroll
        for (int mf = 0; mf < 4; mf++) {
            int ia = ((ga0 + mf) * 4 + ks) * 32 + lane;
            ah[mf] = g_MAh[ia];
            al[mf] = g_MAl[ia];
        }
#pragma unroll
        for (int nf = 0; nf < 8; nf++) {
            int ib = ((gb0 + nf) * 4 + ks) * 32 + lane;
            uint2 bh = g_MBh[ib], bl = g_MBl[ib];
#pragma unroll
            for (int mf = 0; mf < 4; mf++) mma3(acc[mf][nf], ah[mf], al[mf], bh, bl);
        }
    }
    // direct tile
#pragma unroll
    for (int mf = 0; mf < 4; mf++) {
        int r = i0 + wr * 64 + mf * 16 + lr;
#pragma unroll
        for (int nf = 0; nf < 8; nf++) {
            int j = j0 + wc * 64 + nf * 8 + 2 * lc;
            *(float2*)&C[(size_t)r * NN + j] = make_float2(acc[mf][nf][0], acc[mf][nf][1]);
            *(float2*)&C[(size_t)(r + 8) * NN + j] = make_float2(acc[mf][nf][2], acc[mf][nf][3]);
        }
    }
    if (bx == by) return;
    // mirror: 4 strips of 32 cols via smem transpose
#pragma unroll
    for (int s = 0; s < 4; s++) {
        __syncthreads();
        if (wc == (s >> 1)) {
            int nf0 = (s & 1) * 4;
#pragma unroll
            for (int mf = 0; mf < 4; mf++) {
                int rl = wr * 64 + mf * 16 + lr;
#pragma unroll
                for (int nf = 0; nf < 4; nf++) {
                    int cl = nf * 8 + 2 * lc;
                    T[cl][rl] = acc[mf][nf0 + nf][0];
                    T[cl + 1][rl] = acc[mf][nf0 + nf][1];
                    T[cl][rl + 8] = acc[mf][nf0 + nf][2];
                    T[cl + 1][rl + 8] = acc[mf][nf0 + nf][3];
                }
            }
        }
        __syncthreads();
        int jj = tid >> 2, seg = (tid & 3) * 32;
        size_t base = (size_t)(j0 + s * 32 + jj) * NN + i0 + seg;
#pragma unroll
        for (int q = 0; q < 8; q++)
            *(float4*)&C[base + q * 4] = *(float4*)&T[jj][seg + q * 4];
    }
}

// ================= launch =================
extern "C" void kernel_launch(void* const* d_in, const int* in_sizes, int n_in,
                              void* d_out, int out_size) {
    const float* x        = (const float*)d_in[0];
    const int*   adj_rows = (const int*)d_in[1];
    const int*   adj_cols = (const int*)d_in[2];
    const float* adj_vals = (const float*)d_in[3];
    const float* W1       = (const float*)d_in[4];
    const float* W2       = (const float*)d_in[5];
    const float* W3       = (const float*)d_in[6];
    const float* dense_W  = (const float*)d_in[7];
    const float* dense_b  = (const float*)d_in[8];
    const float* dense1_W = (const float*)d_in[9];
    const float* dense1_b = (const float*)d_in[10];

    float* out = (float*)d_out;
    float* adj = out;
    float* o6  = adj + (size_t)NN * NN;
    float* mu  = o6 + (size_t)NN * O6;
    float* lv  = mu + (size_t)NN * H3D;

    void *p_xw1, *p_h1, *p_ah1;
    cudaGetSymbolAddress(&p_xw1, g_xw1);
    cudaGetSymbolAddress(&p_h1, g_h1);
    cudaGetSymbolAddress(&p_ah1, g_ah1);

    // prep packs + small weights
    wcat_kernel<<<H1D, H2D>>>(W2, W3, dense_W);
    pack_x_kernel<<<512, 1024>>>(x);
    pack_w1_kernel<<<32, 1024>>>(W1);

    // xw1 = x @ W1 (bf16 fragment GEMM)
    xw1_mma_kernel<<<dim3(2, 64), 256>>>((float*)p_xw1);

    // CSR
    hist_kernel<<<NE / 1024, 256>>>(adj_rows);
    scan_kernel<<<1, 1024>>>();
    scatter_kernel<<<NE / 256, 256>>>(adj_rows, adj_cols, adj_vals);

    // SpMMs
    spmm_v4<<<NN / 4, 256>>>((const float*)p_xw1, (float*)p_h1, 1);
    spmm_v4<<<NN / 4, 256>>>((const float*)p_h1, (float*)p_ah1, 0);

    // mu/lv
    ml_kernel<<<NN / 128, 256>>>((const float*)p_ah1, dense_b, mu, lv);

    // pack mu + o6
    pack_mu_kernel<<<512, 384>>>(mu);
    o6_kernel<<<NN / 64, 384>>>(mu, dense1_W, dense1_b, o6);

    // adj_rec
    zzt_kernel<<<dim3(64, 64), 128>>>(adj);
}